// round 5
// baseline (speedup 1.0000x reference)
#include <cuda_runtime.h>
#include <math.h>

#define NB 4
#define NC 128
#define NN 4096
#define NK 9

// ---------------- device scratch ----------------
__device__ __align__(16) float d_WT[128 * 384];     // [c][o] combined weights (P|Q|AW|pad)
__device__ float d_bias[384];
__device__ __align__(16) float d_xx[NB * NN];
__device__ int   d_knn_buf[NB * NN * NK];
__device__ __align__(16) float d_PQA[NB * NN * 384]; // [b][n][o]
__device__ __align__(16) float d_Y[NB * NN * 128];   // [b][n][c]
__device__ __align__(16) float d_Z[NB * 128 * NN];   // [b][o][n]
__device__ float d_gnp_s[16 * NN];
__device__ float d_gnp_q[16 * NN];
__device__ float d_gnm[16], d_gni[16];
__device__ __align__(16) float d_WPT[NB * 128 * 128]; // [b][c][o]
__device__ float d_E[NB * 128];
__device__ float d_bnp_s[128 * 128], d_bnp_q[128 * 128];
__device__ float d_bnm[128], d_bni[128];

// ---------------- f32x2 helpers ----------------
__device__ __forceinline__ unsigned long long pack2(float x, float y) {
    unsigned long long r;
    asm("mov.b64 %0, {%1, %2};" : "=l"(r) : "f"(x), "f"(y));
    return r;
}
__device__ __forceinline__ void fma2(unsigned long long& d, unsigned long long a, unsigned long long b) {
    asm("fma.rn.f32x2 %0, %1, %2, %0;" : "+l"(d) : "l"(a), "l"(b));
}
__device__ __forceinline__ float2 unpk(unsigned long long v) {
    float2 r;
    asm("mov.b64 {%0, %1}, %2;" : "=f"(r.x), "=f"(r.y) : "l"(v));
    return r;
}
__device__ __forceinline__ void cpasync16(void* dst, const void* src) {
    unsigned s = (unsigned)__cvta_generic_to_shared(dst);
    asm volatile("cp.async.cg.shared.global [%0], [%1], 16;" :: "r"(s), "l"(src) : "memory");
}
#define CP_COMMIT() asm volatile("cp.async.commit_group;" ::: "memory")
#define CP_WAIT0()  asm volatile("cp.async.wait_group 0;" ::: "memory")

// key: descending by value, ties -> smaller index first (matches lax.top_k)
__device__ __forceinline__ unsigned long long enckey(float v, int m) {
    unsigned u = __float_as_uint(v);
    unsigned mask = ((int)u < 0) ? 0xFFFFFFFFu : 0x80000000u;
    u ^= mask;
    return ((unsigned long long)u << 32) | (unsigned)(~m);
}

// ---------------- k0: combined weights (transposed) ----------------
__global__ void prep_kernel(const float* __restrict__ w_lin, const float* __restrict__ b_lin,
                            const float* __restrict__ w_aw, const float* __restrict__ b_aw) {
    int i = blockIdx.x * 256 + threadIdx.x;
    if (i >= 384 * 128) return;
    int o = i % 384, c = i / 384;
    float w = 0.f;
    if (o < 128)      w = w_lin[o * 256 + c] + w_lin[o * 256 + 128 + c];
    else if (o < 256) w = w_lin[(o - 128) * 256 + 128 + c];
    else if (o < 292) w = w_aw[(o - 256) * 128 + c];
    d_WT[c * 384 + o] = w;
    if (c == 0) {
        float bv = 0.f;
        if (o < 128) bv = b_lin[o];
        else if (o >= 256 && o < 292) bv = b_aw[o - 256];
        d_bias[o] = bv;
    }
}

// ---------------- k1: xx ----------------
__global__ void xx_kernel(const float* __restrict__ x) {
    int i = blockIdx.x * 256 + threadIdx.x;
    int b = i >> 12, n = i & (NN - 1);
    float s = 0.f;
    #pragma unroll 8
    for (int c = 0; c < 128; c++) {
        float v = x[(b * 128 + c) * NN + n];
        s = fmaf(v, v, s);
    }
    d_xx[i] = s;
}

// ---------------- k2: KNN ----------------
// Block: 32 query rows, 256 threads. Thread = (tr=tid>>4 -> 2 rows, tm=tid&15 -> 8 m).
// cp.async double-buffered m-tiles (128 wide), top-9 lists in smem with register thresholds.
// Dynamic smem layout (floats):
//   xnT  [128][36]        : 4608 floats
//   xmB  [2][16*132]      : 4224 floats
//   xxS  [2][128]         : 256 floats
//   lists[32*16*9] (u64)  : 4608 u64  (offset 9088 floats = 36352B, 8B aligned)
#define KNN_SMEM_BYTES (9088 * 4 + 4608 * 8)

__global__ void __launch_bounds__(256) knn_kernel(const float* __restrict__ x) {
    extern __shared__ float sm[];
    float* xnT = sm;                                      // 4608
    float* xmB = sm + 4608;                               // 4224
    float* xxS = sm + 8832;                               // 256
    unsigned long long* lists = (unsigned long long*)(sm + 9088);

    const int b  = blockIdx.y;
    const int n0 = blockIdx.x * 32;
    const int tid = threadIdx.x;
    const int tr = tid >> 4, tm = tid & 15, r0 = tr * 2;
    const int ccL = tid >> 4;           // cp.async slot: channel within chunk
    const int mlL = (tid & 15) * 8;     // cp.async slot: m offset

    // init lists + load query tile (transposed)
    for (int i = tid; i < 4608; i += 256) lists[i] = 0ull;
    for (int i = tid; i < 4096; i += 256) {
        int c = i >> 5, r = i & 31;
        xnT[c * 36 + r] = x[(b * 128 + c) * NN + n0 + r];
    }

    unsigned long long th0 = 0ull, th1 = 0ull;
    unsigned long long* L0 = lists + ((r0 + 0) * 16 + tm) * 9;
    unsigned long long* L1 = lists + ((r0 + 1) * 16 + tm) * 9;

    // preload (mt=0, ck=0) + xx tile 0
    {
        const float* src = &x[(b * 128 + ccL) * NN + 0 + mlL];
        float* dst = xmB + ccL * 132 + mlL;
        cpasync16(dst, src);
        cpasync16(dst + 4, src + 4);
        if (tid < 32) cpasync16(&xxS[tid * 4], &d_xx[b * NN + tid * 4]);
        CP_COMMIT();
    }

    for (int mt = 0; mt < 32; mt++) {
        const int m0 = mt * 128;
        unsigned long long a00 = 0, a01 = 0, a02 = 0, a03 = 0;
        unsigned long long a10 = 0, a11 = 0, a12 = 0, a13 = 0;

        for (int ck = 0; ck < 8; ck++) {
            CP_WAIT0();
            __syncthreads();
            // issue next prefetch (targets the other buffer; safe after the barrier)
            if (ck < 7) {
                const float* src = &x[(b * 128 + (ck + 1) * 16 + ccL) * NN + m0 + mlL];
                float* dst = xmB + ((ck + 1) & 1) * 2112 + ccL * 132 + mlL;
                cpasync16(dst, src);
                cpasync16(dst + 4, src + 4);
                CP_COMMIT();
            } else if (mt < 31) {
                const int m0n = m0 + 128;
                const float* src = &x[(b * 128 + ccL) * NN + m0n + mlL];
                float* dst = xmB + ccL * 132 + mlL;   // ck=0 -> buffer 0
                cpasync16(dst, src);
                cpasync16(dst + 4, src + 4);
                if (tid < 32) cpasync16(&xxS[((mt + 1) & 1) * 128 + tid * 4],
                                        &d_xx[b * NN + m0n + tid * 4]);
                CP_COMMIT();
            }
            const float* xb = xmB + (ck & 1) * 2112;
            #pragma unroll
            for (int cc = 0; cc < 16; cc++) {
                const float2 av = *(const float2*)(xnT + (ck * 16 + cc) * 36 + r0);
                const ulonglong2* cp0 = (const ulonglong2*)(const void*)(xb + cc * 132 + tm * 8);
                ulonglong2 c0 = cp0[0];
                ulonglong2 c1 = cp0[1];
                unsigned long long ad0 = pack2(av.x, av.x);
                unsigned long long ad1 = pack2(av.y, av.y);
                fma2(a00, ad0, c0.x); fma2(a01, ad0, c0.y);
                fma2(a02, ad0, c1.x); fma2(a03, ad0, c1.y);
                fma2(a10, ad1, c0.x); fma2(a11, ad1, c0.y);
                fma2(a12, ad1, c1.x); fma2(a13, ad1, c1.y);
            }
        }

        // selection for this tile (reads own accs, xxS parity buffer, own smem lists)
        float2 p0 = unpk(a00), p1 = unpk(a01), p2 = unpk(a02), p3 = unpk(a03);
        float v0[8] = {p0.x, p0.y, p1.x, p1.y, p2.x, p2.y, p3.x, p3.y};
        p0 = unpk(a10); p1 = unpk(a11); p2 = unpk(a12); p3 = unpk(a13);
        float v1[8] = {p0.x, p0.y, p1.x, p1.y, p2.x, p2.y, p3.x, p3.y};
        const float* xp = xxS + (mt & 1) * 128 + tm * 8;
        float4 q0 = *(const float4*)xp;
        float4 q1 = *(const float4*)(xp + 4);
        float xx8[8] = {q0.x, q0.y, q0.z, q0.w, q1.x, q1.y, q1.z, q1.w};
        #pragma unroll
        for (int j = 0; j < 8; j++) {
            int m = m0 + tm * 8 + j;
            unsigned long long k0 = enckey(2.f * v0[j] - xx8[j], m);
            if (k0 > th0) {
                unsigned long long key = k0;
                #pragma unroll
                for (int q = 0; q < 9; q++) {
                    unsigned long long cur = L0[q];
                    if (key > cur) { L0[q] = key; key = cur; }
                }
                th0 = L0[8];
            }
            unsigned long long k1 = enckey(2.f * v1[j] - xx8[j], m);
            if (k1 > th1) {
                unsigned long long key = k1;
                #pragma unroll
                for (int q = 0; q < 9; q++) {
                    unsigned long long cur = L1[q];
                    if (key > cur) { L1[q] = key; key = cur; }
                }
                th1 = L1[8];
            }
        }
    }

    // merge 16 sorted lists per row
    __syncthreads();
    if (tid < 32) {
        const unsigned long long* base = lists + tid * 144;
        int h[16];
        #pragma unroll
        for (int l = 0; l < 16; l++) h[l] = 0;
        for (int q = 0; q < 9; q++) {
            unsigned long long best = 0; int bl = 0;
            #pragma unroll
            for (int l = 0; l < 16; l++) {
                if (h[l] < 9) {
                    unsigned long long kk = base[l * 9 + h[l]];
                    if (kk > best) { best = kk; bl = l; }
                }
            }
            h[bl]++;
            d_knn_buf[(b * NN + n0 + tid) * NK + q] = (int)(~(unsigned)best);
        }
    }
}

// ---------------- k3: GEMM A  out[b][n][o] = sum_c WT[c][o]*x[b][c][n] + bias ----------------
__global__ void __launch_bounds__(256) gemmA_kernel(const float* __restrict__ x) {
    int b = blockIdx.y, n0 = blockIdx.x * 128, o0 = blockIdx.z * 128;
    __shared__ __align__(16) float Ws[32 * 132];
    __shared__ __align__(16) float Xs[32 * 132];
    int tx = threadIdx.x & 15, ty = threadIdx.x >> 4;
    float acc[8][8];
    {
        float bias[8];
        #pragma unroll
        for (int i = 0; i < 8; i++) bias[i] = d_bias[o0 + ty * 8 + i];
        #pragma unroll
        for (int j = 0; j < 8; j++)
            #pragma unroll
            for (int i = 0; i < 8; i++) acc[j][i] = bias[i];
    }
    for (int c0 = 0; c0 < 128; c0 += 32) {
        __syncthreads();
        for (int t = threadIdx.x; t < 32 * 128; t += 256) {
            int cc = t >> 7, oo = t & 127;
            Ws[cc * 132 + oo] = d_WT[(c0 + cc) * 384 + o0 + oo];
            Xs[cc * 132 + oo] = x[(b * 128 + c0 + cc) * NN + n0 + oo];
        }
        __syncthreads();
        #pragma unroll
        for (int cc = 0; cc < 32; cc++) {
            float4 w0 = *(const float4*)(Ws + cc * 132 + ty * 8);
            float4 w1 = *(const float4*)(Ws + cc * 132 + ty * 8 + 4);
            #pragma unroll
            for (int j = 0; j < 8; j++) {
                float xv = Xs[cc * 132 + tx + 16 * j];
                acc[j][0] = fmaf(w0.x, xv, acc[j][0]);
                acc[j][1] = fmaf(w0.y, xv, acc[j][1]);
                acc[j][2] = fmaf(w0.z, xv, acc[j][2]);
                acc[j][3] = fmaf(w0.w, xv, acc[j][3]);
                acc[j][4] = fmaf(w1.x, xv, acc[j][4]);
                acc[j][5] = fmaf(w1.y, xv, acc[j][5]);
                acc[j][6] = fmaf(w1.z, xv, acc[j][6]);
                acc[j][7] = fmaf(w1.w, xv, acc[j][7]);
            }
        }
    }
    #pragma unroll
    for (int j = 0; j < 8; j++) {
        int n = n0 + tx + 16 * j;
        float* dp = d_PQA + (b * NN + n) * 384 + o0 + ty * 8;
        *(float4*)dp       = make_float4(acc[j][0], acc[j][1], acc[j][2], acc[j][3]);
        *(float4*)(dp + 4) = make_float4(acc[j][4], acc[j][5], acc[j][6], acc[j][7]);
    }
}

// ---------------- k4: per-point attention ----------------
__global__ void __launch_bounds__(128) attn_kernel(const float* __restrict__ x) {
    int n = blockIdx.x, b = blockIdx.y;
    int c = threadIdx.x, g = c >> 5;
    __shared__ float fS[9 * 132];
    __shared__ float sS[4 * 81];
    __shared__ float awS[36], tS[36];
    __shared__ int idxS[9];
    int base = (b * NN + n) * 384;
    if (c < 9)  idxS[c] = d_knn_buf[(b * NN + n) * NK + c];
    if (c < 36) awS[c] = d_PQA[base + 256 + c];
    __syncthreads();
    float P = d_PQA[base + c];
    float e9[9];
    #pragma unroll
    for (int k = 0; k < 9; k++) {
        float f = P - d_PQA[(b * NN + idxS[k]) * 384 + 128 + c];
        fS[k * 132 + c] = f;
        e9[k] = f > 0.f ? f : expm1f(f);
    }
    if (c < 4) {
        float* row = awS + c * 9;
        float mx = row[0];
        #pragma unroll
        for (int k = 1; k < 9; k++) mx = fmaxf(mx, row[k]);
        float sm = 0.f;
        #pragma unroll
        for (int k = 0; k < 9; k++) { float e = expf(row[k] - mx); row[k] = e; sm += e; }
        float inv = 1.f / sm;
        #pragma unroll
        for (int k = 0; k < 9; k++) row[k] *= inv;
    }
    __syncthreads();
    for (int t = c; t < 324; t += 128) {
        int g2 = t / 81, p = t % 81, k = p / 9, j = p % 9;
        const float* fa = fS + k * 132 + g2 * 32;
        const float* fb = fS + j * 132 + g2 * 32;
        float s = 0.f;
        #pragma unroll
        for (int q = 0; q < 32; q++) s = fmaf(fa[q], fb[q], s);
        sS[g2 * 81 + p] = s * 0.17677669529663689f;
    }
    __syncthreads();
    if (c < 36) {
        float* row = sS + (c / 9) * 81 + (c % 9) * 9;
        float mx = row[0];
        #pragma unroll
        for (int j = 1; j < 9; j++) mx = fmaxf(mx, row[j]);
        float sm = 0.f;
        #pragma unroll
        for (int j = 0; j < 9; j++) { float e = expf(row[j] - mx); row[j] = e; sm += e; }
        float inv = 1.f / sm;
        #pragma unroll
        for (int j = 0; j < 9; j++) row[j] *= inv;
    }
    __syncthreads();
    if (c < 36) {
        int g2 = c / 9, j = c % 9;
        float tv = 0.f;
        #pragma unroll
        for (int k = 0; k < 9; k++) tv = fmaf(awS[g2 * 9 + k], sS[g2 * 81 + k * 9 + j], tv);
        tS[c] = tv;
    }
    __syncthreads();
    float lf = 0.f;
    #pragma unroll
    for (int j = 0; j < 9; j++) lf = fmaf(tS[g * 9 + j], e9[j], lf);
    float yv = lf + x[(b * 128 + c) * NN + n];
    d_Y[(b * NN + n) * 128 + c] = yv;
    float s1 = yv, s2 = yv * yv;
    #pragma unroll
    for (int off = 16; off; off >>= 1) {
        s1 += __shfl_xor_sync(0xffffffffu, s1, off);
        s2 += __shfl_xor_sync(0xffffffffu, s2, off);
    }
    if ((c & 31) == 0) {
        d_gnp_s[(b * 4 + g) * NN + n] = s1;
        d_gnp_q[(b * 4 + g) * NN + n] = s2;
    }
}

// ---------------- k5: GN stats (deterministic) ----------------
__global__ void gn_stats_kernel() {
    int bg = blockIdx.x;
    __shared__ double sh[256], sh2[256];
    double s = 0.0, q = 0.0;
    for (int i = threadIdx.x; i < NN; i += 256) {
        s += (double)d_gnp_s[bg * NN + i];
        q += (double)d_gnp_q[bg * NN + i];
    }
    sh[threadIdx.x] = s; sh2[threadIdx.x] = q;
    __syncthreads();
    for (int off = 128; off; off >>= 1) {
        if (threadIdx.x < off) { sh[threadIdx.x] += sh[threadIdx.x + off]; sh2[threadIdx.x] += sh2[threadIdx.x + off]; }
        __syncthreads();
    }
    if (threadIdx.x == 0) {
        double cnt = 32.0 * NN;
        double mean = sh[0] / cnt;
        double var = sh2[0] / cnt - mean * mean;
        d_gnm[bg] = (float)mean;
        d_gni[bg] = (float)(1.0 / sqrt(var + 1e-5));
    }
}

// ---------------- k6: fold GN into conv weights ----------------
__global__ void prepw_kernel(const float* __restrict__ conv_w, const float* __restrict__ conv_b,
                             const float* __restrict__ gn_g, const float* __restrict__ gn_b) {
    int b = blockIdx.x, o = threadIdx.x;
    float e = conv_b[o];
    for (int c = 0; c < 128; c++) {
        int g = c >> 5;
        float inv = d_gni[b * 4 + g];
        float A = gn_g[c] * inv;
        float D = gn_b[c] - d_gnm[b * 4 + g] * A;
        float w = conv_w[o * 128 + c];
        e = fmaf(w, D, e);
        d_WPT[(b * 128 + c) * 128 + o] = w * A;
    }
    d_E[b * 128 + o] = e;
}

// ---------------- k7: GEMM B  z[b][o][n] = sum_c WPT[b][c][o]*Y[b][n][c] + E ----------------
__global__ void __launch_bounds__(256) gemmB_kernel() {
    int b = blockIdx.y, n0 = blockIdx.x * 128;
    __shared__ __align__(16) float Ws[32 * 132];
    __shared__ __align__(16) float Ys[128 * 33];
    int tx = threadIdx.x & 15, ty = threadIdx.x >> 4;
    float acc[8][8];
    {
        float eb[8];
        #pragma unroll
        for (int i = 0; i < 8; i++) eb[i] = d_E[b * 128 + ty * 8 + i];
        #pragma unroll
        for (int j = 0; j < 8; j++)
            #pragma unroll
            for (int i = 0; i < 8; i++) acc[j][i] = eb[i];
    }
    for (int c0 = 0; c0 < 128; c0 += 32) {
        __syncthreads();
        for (int t = threadIdx.x; t < 32 * 128; t += 256) {
            int cc = t >> 7, oo = t & 127;
            Ws[cc * 132 + oo] = d_WPT[(b * 128 + c0 + cc) * 128 + oo];
            int nl = t >> 5, cl = t & 31;
            Ys[nl * 33 + cl] = d_Y[(b * NN + n0 + nl) * 128 + c0 + cl];
        }
        __syncthreads();
        #pragma unroll
        for (int cc = 0; cc < 32; cc++) {
            float4 w0 = *(const float4*)(Ws + cc * 132 + ty * 8);
            float4 w1 = *(const float4*)(Ws + cc * 132 + ty * 8 + 4);
            #pragma unroll
            for (int j = 0; j < 8; j++) {
                float yv = Ys[(tx + 16 * j) * 33 + cc];
                acc[j][0] = fmaf(w0.x, yv, acc[j][0]);
                acc[j][1] = fmaf(w0.y, yv, acc[j][1]);
                acc[j][2] = fmaf(w0.z, yv, acc[j][2]);
                acc[j][3] = fmaf(w0.w, yv, acc[j][3]);
                acc[j][4] = fmaf(w1.x, yv, acc[j][4]);
                acc[j][5] = fmaf(w1.y, yv, acc[j][5]);
                acc[j][6] = fmaf(w1.z, yv, acc[j][6]);
                acc[j][7] = fmaf(w1.w, yv, acc[j][7]);
            }
        }
    }
    #pragma unroll
    for (int j = 0; j < 8; j++) {
        int n = n0 + tx + 16 * j;
        #pragma unroll
        for (int i = 0; i < 8; i++)
            d_Z[(b * 128 + ty * 8 + i) * NN + n] = acc[j][i];
    }
    // deterministic per-block BN partials
    float* red = Ys;
    __syncthreads();
    #pragma unroll
    for (int i = 0; i < 8; i++) {
        float s = 0.f, q = 0.f;
        #pragma unroll
        for (int j = 0; j < 8; j++) { s += acc[j][i]; q = fmaf(acc[j][i], acc[j][i], q); }
        red[(ty * 8 + i) * 16 + tx] = s;
        red[2048 + (ty * 8 + i) * 16 + tx] = q;
    }
    __syncthreads();
    if (threadIdx.x < 128) {
        int o = threadIdx.x;
        float s = 0.f, q = 0.f;
        #pragma unroll
        for (int t = 0; t < 16; t++) { s += red[o * 16 + t]; q += red[2048 + o * 16 + t]; }
        int blk = blockIdx.y * 32 + blockIdx.x;
        d_bnp_s[o * 128 + blk] = s;
        d_bnp_q[o * 128 + blk] = q;
    }
}

// ---------------- k8: BN stats ----------------
__global__ void bn_stats_kernel() {
    int o = threadIdx.x;
    double s = 0.0, q = 0.0;
    for (int k = 0; k < 128; k++) { s += (double)d_bnp_s[o * 128 + k]; q += (double)d_bnp_q[o * 128 + k]; }
    double cnt = (double)(NB * NN);
    double mean = s / cnt;
    double var = q / cnt - mean * mean;
    d_bnm[o] = (float)mean;
    d_bni[o] = (float)(1.0 / sqrt(var + 1e-5));
}

// ---------------- k9: BN apply + relu ----------------
__global__ void final_kernel(const float* __restrict__ bn_g, const float* __restrict__ bn_b,
                             float* __restrict__ out) {
    int i = blockIdx.x * 256 + threadIdx.x;
    int o = (i >> 12) & 127;
    float v = (d_Z[i] - d_bnm[o]) * d_bni[o] * bn_g[o] + bn_b[o];
    out[i] = fmaxf(v, 0.f);
}

extern "C" void kernel_launch(void* const* d_in, const int* in_sizes, int n_in,
                              void* d_out, int out_size) {
    const float* x      = (const float*)d_in[0];
    const float* w_lin  = (const float*)d_in[1];
    const float* b_lin  = (const float*)d_in[2];
    const float* w_aw   = (const float*)d_in[3];
    const float* b_aw   = (const float*)d_in[4];
    const float* gn_g   = (const float*)d_in[5];
    const float* gn_b   = (const float*)d_in[6];
    const float* conv_w = (const float*)d_in[7];
    const float* conv_b = (const float*)d_in[8];
    const float* bn_g   = (const float*)d_in[9];
    const float* bn_b   = (const float*)d_in[10];
    float* out = (float*)d_out;

    cudaFuncSetAttribute(knn_kernel, cudaFuncAttributeMaxDynamicSharedMemorySize, KNN_SMEM_BYTES);

    prep_kernel<<<192, 256>>>(w_lin, b_lin, w_aw, b_aw);
    xx_kernel<<<64, 256>>>(x);
    knn_kernel<<<dim3(128, 4), 256, KNN_SMEM_BYTES>>>(x);
    gemmA_kernel<<<dim3(32, 4, 3), 256>>>(x);
    attn_kernel<<<dim3(4096, 4), 128>>>(x);
    gn_stats_kernel<<<16, 256>>>();
    prepw_kernel<<<4, 128>>>(conv_w, conv_b, gn_g, gn_b);
    gemmB_kernel<<<dim3(32, 4), 256>>>();
    bn_stats_kernel<<<1, 128>>>();
    final_kernel<<<8192, 256>>>(bn_g, bn_b, out);
}

// round 6
// speedup vs baseline: 1.4422x; 1.4422x over previous
#include <cuda_runtime.h>
#include <math.h>

#define NB 4
#define NC 128
#define NN 4096
#define NK 9

// ---------------- device scratch ----------------
__device__ __align__(16) float d_WT[128 * 384];     // [c][o] combined weights (P|Q|AW|pad)
__device__ float d_bias[384];
__device__ __align__(16) float d_xx[NB * NN];
__device__ int   d_knn_buf[NB * NN * NK];
__device__ __align__(16) float d_PQA[NB * NN * 384]; // [b][n][o]
__device__ __align__(16) float d_Y[NB * NN * 128];   // [b][n][c]
__device__ __align__(16) float d_Z[NB * 128 * NN];   // [b][o][n]
__device__ float d_gnp_s[16 * NN];
__device__ float d_gnp_q[16 * NN];
__device__ float d_gnm[16], d_gni[16];
__device__ __align__(16) float d_WPT[NB * 128 * 128]; // [b][c][o]
__device__ float d_E[NB * 128];
__device__ float d_bnp_s[128 * 128], d_bnp_q[128 * 128];
__device__ float d_bnm[128], d_bni[128];

// ---------------- f32x2 helpers ----------------
__device__ __forceinline__ unsigned long long pack2(float x, float y) {
    unsigned long long r;
    asm("mov.b64 %0, {%1, %2};" : "=l"(r) : "f"(x), "f"(y));
    return r;
}
__device__ __forceinline__ void fma2(unsigned long long& d, unsigned long long a, unsigned long long b) {
    asm("fma.rn.f32x2 %0, %1, %2, %0;" : "+l"(d) : "l"(a), "l"(b));
}
__device__ __forceinline__ float2 unpk(unsigned long long v) {
    float2 r;
    asm("mov.b64 {%0, %1}, %2;" : "=f"(r.x), "=f"(r.y) : "l"(v));
    return r;
}
__device__ __forceinline__ void cpasync16(void* dst, const void* src) {
    unsigned s = (unsigned)__cvta_generic_to_shared(dst);
    asm volatile("cp.async.cg.shared.global [%0], [%1], 16;" :: "r"(s), "l"(src) : "memory");
}
#define CP_COMMIT() asm volatile("cp.async.commit_group;" ::: "memory")
#define CP_WAIT0()  asm volatile("cp.async.wait_group 0;" ::: "memory")

// key: descending by value, ties -> smaller index first (matches lax.top_k)
__device__ __forceinline__ unsigned long long enckey(float v, int m) {
    unsigned u = __float_as_uint(v);
    unsigned mask = ((int)u < 0) ? 0xFFFFFFFFu : 0x80000000u;
    u ^= mask;
    return ((unsigned long long)u << 32) | (unsigned)(~m);
}

// ---------------- k0: combined weights (transposed) ----------------
__global__ void prep_kernel(const float* __restrict__ w_lin, const float* __restrict__ b_lin,
                            const float* __restrict__ w_aw, const float* __restrict__ b_aw) {
    int i = blockIdx.x * 256 + threadIdx.x;
    if (i >= 384 * 128) return;
    int o = i % 384, c = i / 384;
    float w = 0.f;
    if (o < 128)      w = w_lin[o * 256 + c] + w_lin[o * 256 + 128 + c];
    else if (o < 256) w = w_lin[(o - 128) * 256 + 128 + c];
    else if (o < 292) w = w_aw[(o - 256) * 128 + c];
    d_WT[c * 384 + o] = w;
    if (c == 0) {
        float bv = 0.f;
        if (o < 128) bv = b_lin[o];
        else if (o >= 256 && o < 292) bv = b_aw[o - 256];
        d_bias[o] = bv;
    }
}

// ---------------- k1: xx ----------------
__global__ void xx_kernel(const float* __restrict__ x) {
    int i = blockIdx.x * 256 + threadIdx.x;
    int b = i >> 12, n = i & (NN - 1);
    float s = 0.f;
    #pragma unroll 8
    for (int c = 0; c < 128; c++) {
        float v = x[(b * 128 + c) * NN + n];
        s = fmaf(v, v, s);
    }
    d_xx[i] = s;
}

// slot-shift dummy so knn lands in the ncu-captured launch position
__global__ void dummy_kernel() {}

// ---------------- k2: KNN ----------------
// Block: 32 query rows, 256 threads. Thread = (tr=tid>>4 -> 2 rows, tm=tid&15).
// Each thread covers m-columns {tm*4..tm*4+3} and {64+tm*4..64+tm*4+3} of the
// 128-wide m-tile: every LDS.128 phase (8 threads) then spans exactly 128
// contiguous bytes -> conflict-free smem reads (the R4 layout was 2-way
// conflicted on every B load).
// Dynamic smem layout (floats):
//   xnT  [128][36]        : 4608 floats
//   xmB  [2][16*132]      : 4224 floats
//   xxS  [2][128]         : 256 floats
//   lists[32*16*9] (u64)  : 4608 u64  (offset 9088 floats, 8B aligned)
#define KNN_SMEM_BYTES (9088 * 4 + 4608 * 8)

__global__ void __launch_bounds__(256) knn_kernel(const float* __restrict__ x) {
    extern __shared__ float sm[];
    float* xnT = sm;                                      // 4608
    float* xmB = sm + 4608;                               // 4224
    float* xxS = sm + 8832;                               // 256
    unsigned long long* lists = (unsigned long long*)(sm + 9088);

    const int b  = blockIdx.y;
    const int n0 = blockIdx.x * 32;
    const int tid = threadIdx.x;
    const int tr = tid >> 4, tm = tid & 15, r0 = tr * 2;
    const int ccL = tid >> 4;           // cp.async slot: channel within chunk
    const int mlL = (tid & 15) * 8;     // cp.async slot: m offset

    // init lists + load query tile (transposed)
    for (int i = tid; i < 4608; i += 256) lists[i] = 0ull;
    for (int i = tid; i < 4096; i += 256) {
        int c = i >> 5, r = i & 31;
        xnT[c * 36 + r] = x[(b * 128 + c) * NN + n0 + r];
    }

    unsigned long long th0 = 0ull, th1 = 0ull;
    unsigned long long* L0 = lists + ((r0 + 0) * 16 + tm) * 9;
    unsigned long long* L1 = lists + ((r0 + 1) * 16 + tm) * 9;

    // preload (mt=0, ck=0) + xx tile 0
    {
        const float* src = &x[(b * 128 + ccL) * NN + 0 + mlL];
        float* dst = xmB + ccL * 132 + mlL;
        cpasync16(dst, src);
        cpasync16(dst + 4, src + 4);
        if (tid < 32) cpasync16(&xxS[tid * 4], &d_xx[b * NN + tid * 4]);
        CP_COMMIT();
    }

    for (int mt = 0; mt < 32; mt++) {
        const int m0 = mt * 128;
        unsigned long long a00 = 0, a01 = 0, a02 = 0, a03 = 0;
        unsigned long long a10 = 0, a11 = 0, a12 = 0, a13 = 0;

        for (int ck = 0; ck < 8; ck++) {
            CP_WAIT0();
            __syncthreads();
            // issue next prefetch (targets the other buffer; safe after the barrier)
            if (ck < 7) {
                const float* src = &x[(b * 128 + (ck + 1) * 16 + ccL) * NN + m0 + mlL];
                float* dst = xmB + ((ck + 1) & 1) * 2112 + ccL * 132 + mlL;
                cpasync16(dst, src);
                cpasync16(dst + 4, src + 4);
                CP_COMMIT();
            } else if (mt < 31) {
                const int m0n = m0 + 128;
                const float* src = &x[(b * 128 + ccL) * NN + m0n + mlL];
                float* dst = xmB + ccL * 132 + mlL;   // ck=0 -> buffer 0
                cpasync16(dst, src);
                cpasync16(dst + 4, src + 4);
                if (tid < 32) cpasync16(&xxS[((mt + 1) & 1) * 128 + tid * 4],
                                        &d_xx[b * NN + m0n + tid * 4]);
                CP_COMMIT();
            }
            const float* xb = xmB + (ck & 1) * 2112;
            #pragma unroll
            for (int cc = 0; cc < 16; cc++) {
                const float2 av = *(const float2*)(xnT + (ck * 16 + cc) * 36 + r0);
                // conflict-free: two float4 groups at tm*4 and 64+tm*4
                ulonglong2 c0 = *(const ulonglong2*)(const void*)(xb + cc * 132 + tm * 4);
                ulonglong2 c1 = *(const ulonglong2*)(const void*)(xb + cc * 132 + 64 + tm * 4);
                unsigned long long ad0 = pack2(av.x, av.x);
                unsigned long long ad1 = pack2(av.y, av.y);
                fma2(a00, ad0, c0.x); fma2(a01, ad0, c0.y);
                fma2(a02, ad0, c1.x); fma2(a03, ad0, c1.y);
                fma2(a10, ad1, c0.x); fma2(a11, ad1, c0.y);
                fma2(a12, ad1, c1.x); fma2(a13, ad1, c1.y);
            }
        }

        // selection: acc lanes map to m = m0+tm*4+{0..3} (c0) and m0+64+tm*4+{0..3} (c1)
        float2 p0 = unpk(a00), p1 = unpk(a01), p2 = unpk(a02), p3 = unpk(a03);
        float v0[8] = {p0.x, p0.y, p1.x, p1.y, p2.x, p2.y, p3.x, p3.y};
        p0 = unpk(a10); p1 = unpk(a11); p2 = unpk(a12); p3 = unpk(a13);
        float v1[8] = {p0.x, p0.y, p1.x, p1.y, p2.x, p2.y, p3.x, p3.y};
        const float* xp = xxS + (mt & 1) * 128;
        float4 q0 = *(const float4*)(xp + tm * 4);
        float4 q1 = *(const float4*)(xp + 64 + tm * 4);
        float xx8[8] = {q0.x, q0.y, q0.z, q0.w, q1.x, q1.y, q1.z, q1.w};
        int mb[8];
        #pragma unroll
        for (int j = 0; j < 4; j++) { mb[j] = m0 + tm * 4 + j; mb[4 + j] = m0 + 64 + tm * 4 + j; }
        #pragma unroll
        for (int j = 0; j < 8; j++) {
            unsigned long long k0 = enckey(2.f * v0[j] - xx8[j], mb[j]);
            if (k0 > th0) {
                unsigned long long key = k0;
                #pragma unroll
                for (int q = 0; q < 9; q++) {
                    unsigned long long cur = L0[q];
                    if (key > cur) { L0[q] = key; key = cur; }
                }
                th0 = L0[8];
            }
            unsigned long long k1 = enckey(2.f * v1[j] - xx8[j], mb[j]);
            if (k1 > th1) {
                unsigned long long key = k1;
                #pragma unroll
                for (int q = 0; q < 9; q++) {
                    unsigned long long cur = L1[q];
                    if (key > cur) { L1[q] = key; key = cur; }
                }
                th1 = L1[8];
            }
        }
    }

    // merge 16 sorted lists per row
    __syncthreads();
    if (tid < 32) {
        const unsigned long long* base = lists + tid * 144;
        int h[16];
        #pragma unroll
        for (int l = 0; l < 16; l++) h[l] = 0;
        for (int q = 0; q < 9; q++) {
            unsigned long long best = 0; int bl = 0;
            #pragma unroll
            for (int l = 0; l < 16; l++) {
                if (h[l] < 9) {
                    unsigned long long kk = base[l * 9 + h[l]];
                    if (kk > best) { best = kk; bl = l; }
                }
            }
            h[bl]++;
            d_knn_buf[(b * NN + n0 + tid) * NK + q] = (int)(~(unsigned)best);
        }
    }
}

// ---------------- k3: GEMM A  out[b][n][o] = sum_c WT[c][o]*x[b][c][n] + bias ----------------
__global__ void __launch_bounds__(256) gemmA_kernel(const float* __restrict__ x) {
    int b = blockIdx.y, n0 = blockIdx.x * 128, o0 = blockIdx.z * 128;
    __shared__ __align__(16) float Ws[32 * 132];
    __shared__ __align__(16) float Xs[32 * 132];
    int tx = threadIdx.x & 15, ty = threadIdx.x >> 4;
    float acc[8][8];
    {
        float bias[8];
        #pragma unroll
        for (int i = 0; i < 8; i++) bias[i] = d_bias[o0 + ty * 8 + i];
        #pragma unroll
        for (int j = 0; j < 8; j++)
            #pragma unroll
            for (int i = 0; i < 8; i++) acc[j][i] = bias[i];
    }
    for (int c0 = 0; c0 < 128; c0 += 32) {
        __syncthreads();
        for (int t = threadIdx.x; t < 32 * 128; t += 256) {
            int cc = t >> 7, oo = t & 127;
            Ws[cc * 132 + oo] = d_WT[(c0 + cc) * 384 + o0 + oo];
            Xs[cc * 132 + oo] = x[(b * 128 + c0 + cc) * NN + n0 + oo];
        }
        __syncthreads();
        #pragma unroll
        for (int cc = 0; cc < 32; cc++) {
            float4 w0 = *(const float4*)(Ws + cc * 132 + ty * 8);
            float4 w1 = *(const float4*)(Ws + cc * 132 + ty * 8 + 4);
            #pragma unroll
            for (int j = 0; j < 8; j++) {
                float xv = Xs[cc * 132 + tx + 16 * j];
                acc[j][0] = fmaf(w0.x, xv, acc[j][0]);
                acc[j][1] = fmaf(w0.y, xv, acc[j][1]);
                acc[j][2] = fmaf(w0.z, xv, acc[j][2]);
                acc[j][3] = fmaf(w0.w, xv, acc[j][3]);
                acc[j][4] = fmaf(w1.x, xv, acc[j][4]);
                acc[j][5] = fmaf(w1.y, xv, acc[j][5]);
                acc[j][6] = fmaf(w1.z, xv, acc[j][6]);
                acc[j][7] = fmaf(w1.w, xv, acc[j][7]);
            }
        }
    }
    #pragma unroll
    for (int j = 0; j < 8; j++) {
        int n = n0 + tx + 16 * j;
        float* dp = d_PQA + (b * NN + n) * 384 + o0 + ty * 8;
        *(float4*)dp       = make_float4(acc[j][0], acc[j][1], acc[j][2], acc[j][3]);
        *(float4*)(dp + 4) = make_float4(acc[j][4], acc[j][5], acc[j][6], acc[j][7]);
    }
}

// ---------------- k4: per-point attention ----------------
__global__ void __launch_bounds__(128) attn_kernel(const float* __restrict__ x) {
    int n = blockIdx.x, b = blockIdx.y;
    int c = threadIdx.x, g = c >> 5;
    __shared__ float fS[9 * 132];
    __shared__ float sS[4 * 81];
    __shared__ float awS[36], tS[36];
    __shared__ int idxS[9];
    int base = (b * NN + n) * 384;
    if (c < 9)  idxS[c] = d_knn_buf[(b * NN + n) * NK + c];
    if (c < 36) awS[c] = d_PQA[base + 256 + c];
    __syncthreads();
    float P = d_PQA[base + c];
    float e9[9];
    #pragma unroll
    for (int k = 0; k < 9; k++) {
        float f = P - d_PQA[(b * NN + idxS[k]) * 384 + 128 + c];
        fS[k * 132 + c] = f;
        e9[k] = f > 0.f ? f : expm1f(f);
    }
    if (c < 4) {
        float* row = awS + c * 9;
        float mx = row[0];
        #pragma unroll
        for (int k = 1; k < 9; k++) mx = fmaxf(mx, row[k]);
        float sm = 0.f;
        #pragma unroll
        for (int k = 0; k < 9; k++) { float e = expf(row[k] - mx); row[k] = e; sm += e; }
        float inv = 1.f / sm;
        #pragma unroll
        for (int k = 0; k < 9; k++) row[k] *= inv;
    }
    __syncthreads();
    for (int t = c; t < 324; t += 128) {
        int g2 = t / 81, p = t % 81, k = p / 9, j = p % 9;
        const float* fa = fS + k * 132 + g2 * 32;
        const float* fb = fS + j * 132 + g2 * 32;
        float s = 0.f;
        #pragma unroll
        for (int q = 0; q < 32; q++) s = fmaf(fa[q], fb[q], s);
        sS[g2 * 81 + p] = s * 0.17677669529663689f;
    }
    __syncthreads();
    if (c < 36) {
        float* row = sS + (c / 9) * 81 + (c % 9) * 9;
        float mx = row[0];
        #pragma unroll
        for (int j = 1; j < 9; j++) mx = fmaxf(mx, row[j]);
        float sm = 0.f;
        #pragma unroll
        for (int j = 0; j < 9; j++) { float e = expf(row[j] - mx); row[j] = e; sm += e; }
        float inv = 1.f / sm;
        #pragma unroll
        for (int j = 0; j < 9; j++) row[j] *= inv;
    }
    __syncthreads();
    if (c < 36) {
        int g2 = c / 9, j = c % 9;
        float tv = 0.f;
        #pragma unroll
        for (int k = 0; k < 9; k++) tv = fmaf(awS[g2 * 9 + k], sS[g2 * 81 + k * 9 + j], tv);
        tS[c] = tv;
    }
    __syncthreads();
    float lf = 0.f;
    #pragma unroll
    for (int j = 0; j < 9; j++) lf = fmaf(tS[g * 9 + j], e9[j], lf);
    float yv = lf + x[(b * 128 + c) * NN + n];
    d_Y[(b * NN + n) * 128 + c] = yv;
    float s1 = yv, s2 = yv * yv;
    #pragma unroll
    for (int off = 16; off; off >>= 1) {
        s1 += __shfl_xor_sync(0xffffffffu, s1, off);
        s2 += __shfl_xor_sync(0xffffffffu, s2, off);
    }
    if ((c & 31) == 0) {
        d_gnp_s[(b * 4 + g) * NN + n] = s1;
        d_gnp_q[(b * 4 + g) * NN + n] = s2;
    }
}

// ---------------- k5: GN stats (deterministic) ----------------
__global__ void gn_stats_kernel() {
    int bg = blockIdx.x;
    __shared__ double sh[256], sh2[256];
    double s = 0.0, q = 0.0;
    for (int i = threadIdx.x; i < NN; i += 256) {
        s += (double)d_gnp_s[bg * NN + i];
        q += (double)d_gnp_q[bg * NN + i];
    }
    sh[threadIdx.x] = s; sh2[threadIdx.x] = q;
    __syncthreads();
    for (int off = 128; off; off >>= 1) {
        if (threadIdx.x < off) { sh[threadIdx.x] += sh[threadIdx.x + off]; sh2[threadIdx.x] += sh2[threadIdx.x + off]; }
        __syncthreads();
    }
    if (threadIdx.x == 0) {
        double cnt = 32.0 * NN;
        double mean = sh[0] / cnt;
        double var = sh2[0] / cnt - mean * mean;
        d_gnm[bg] = (float)mean;
        d_gni[bg] = (float)(1.0 / sqrt(var + 1e-5));
    }
}

// ---------------- k6: fold GN into conv weights ----------------
__global__ void prepw_kernel(const float* __restrict__ conv_w, const float* __restrict__ conv_b,
                             const float* __restrict__ gn_g, const float* __restrict__ gn_b) {
    int b = blockIdx.x, o = threadIdx.x;
    float e = conv_b[o];
    for (int c = 0; c < 128; c++) {
        int g = c >> 5;
        float inv = d_gni[b * 4 + g];
        float A = gn_g[c] * inv;
        float D = gn_b[c] - d_gnm[b * 4 + g] * A;
        float w = conv_w[o * 128 + c];
        e = fmaf(w, D, e);
        d_WPT[(b * 128 + c) * 128 + o] = w * A;
    }
    d_E[b * 128 + o] = e;
}

// ---------------- k7: GEMM B  z[b][o][n] = sum_c WPT[b][c][o]*Y[b][n][c] + E ----------------
__global__ void __launch_bounds__(256) gemmB_kernel() {
    int b = blockIdx.y, n0 = blockIdx.x * 128;
    __shared__ __align__(16) float Ws[32 * 132];
    __shared__ __align__(16) float Ys[128 * 33];
    int tx = threadIdx.x & 15, ty = threadIdx.x >> 4;
    float acc[8][8];
    {
        float eb[8];
        #pragma unroll
        for (int i = 0; i < 8; i++) eb[i] = d_E[b * 128 + ty * 8 + i];
        #pragma unroll
        for (int j = 0; j < 8; j++)
            #pragma unroll
            for (int i = 0; i < 8; i++) acc[j][i] = eb[i];
    }
    for (int c0 = 0; c0 < 128; c0 += 32) {
        __syncthreads();
        for (int t = threadIdx.x; t < 32 * 128; t += 256) {
            int cc = t >> 7, oo = t & 127;
            Ws[cc * 132 + oo] = d_WPT[(b * 128 + c0 + cc) * 128 + oo];
            int nl = t >> 5, cl = t & 31;
            Ys[nl * 33 + cl] = d_Y[(b * NN + n0 + nl) * 128 + c0 + cl];
        }
        __syncthreads();
        #pragma unroll
        for (int cc = 0; cc < 32; cc++) {
            float4 w0 = *(const float4*)(Ws + cc * 132 + ty * 8);
            float4 w1 = *(const float4*)(Ws + cc * 132 + ty * 8 + 4);
            #pragma unroll
            for (int j = 0; j < 8; j++) {
                float yv = Ys[(tx + 16 * j) * 33 + cc];
                acc[j][0] = fmaf(w0.x, yv, acc[j][0]);
                acc[j][1] = fmaf(w0.y, yv, acc[j][1]);
                acc[j][2] = fmaf(w0.z, yv, acc[j][2]);
                acc[j][3] = fmaf(w0.w, yv, acc[j][3]);
                acc[j][4] = fmaf(w1.x, yv, acc[j][4]);
                acc[j][5] = fmaf(w1.y, yv, acc[j][5]);
                acc[j][6] = fmaf(w1.z, yv, acc[j][6]);
                acc[j][7] = fmaf(w1.w, yv, acc[j][7]);
            }
        }
    }
    #pragma unroll
    for (int j = 0; j < 8; j++) {
        int n = n0 + tx + 16 * j;
        #pragma unroll
        for (int i = 0; i < 8; i++)
            d_Z[(b * 128 + ty * 8 + i) * NN + n] = acc[j][i];
    }
    // deterministic per-block BN partials
    float* red = Ys;
    __syncthreads();
    #pragma unroll
    for (int i = 0; i < 8; i++) {
        float s = 0.f, q = 0.f;
        #pragma unroll
        for (int j = 0; j < 8; j++) { s += acc[j][i]; q = fmaf(acc[j][i], acc[j][i], q); }
        red[(ty * 8 + i) * 16 + tx] = s;
        red[2048 + (ty * 8 + i) * 16 + tx] = q;
    }
    __syncthreads();
    if (threadIdx.x < 128) {
        int o = threadIdx.x;
        float s = 0.f, q = 0.f;
        #pragma unroll
        for (int t = 0; t < 16; t++) { s += red[o * 16 + t]; q += red[2048 + o * 16 + t]; }
        int blk = blockIdx.y * 32 + blockIdx.x;
        d_bnp_s[o * 128 + blk] = s;
        d_bnp_q[o * 128 + blk] = q;
    }
}

// ---------------- k8: BN stats ----------------
__global__ void bn_stats_kernel() {
    int o = threadIdx.x;
    double s = 0.0, q = 0.0;
    for (int k = 0; k < 128; k++) { s += (double)d_bnp_s[o * 128 + k]; q += (double)d_bnp_q[o * 128 + k]; }
    double cnt = (double)(NB * NN);
    double mean = s / cnt;
    double var = q / cnt - mean * mean;
    d_bnm[o] = (float)mean;
    d_bni[o] = (float)(1.0 / sqrt(var + 1e-5));
}

// ---------------- k9: BN apply + relu ----------------
__global__ void final_kernel(const float* __restrict__ bn_g, const float* __restrict__ bn_b,
                             float* __restrict__ out) {
    int i = blockIdx.x * 256 + threadIdx.x;
    int o = (i >> 12) & 127;
    float v = (d_Z[i] - d_bnm[o]) * d_bni[o] * bn_g[o] + bn_b[o];
    out[i] = fmaxf(v, 0.f);
}

extern "C" void kernel_launch(void* const* d_in, const int* in_sizes, int n_in,
                              void* d_out, int out_size) {
    const float* x      = (const float*)d_in[0];
    const float* w_lin  = (const float*)d_in[1];
    const float* b_lin  = (const float*)d_in[2];
    const float* w_aw   = (const float*)d_in[3];
    const float* b_aw   = (const float*)d_in[4];
    const float* gn_g   = (const float*)d_in[5];
    const float* gn_b   = (const float*)d_in[6];
    const float* conv_w = (const float*)d_in[7];
    const float* conv_b = (const float*)d_in[8];
    const float* bn_g   = (const float*)d_in[9];
    const float* bn_b   = (const float*)d_in[10];
    float* out = (float*)d_out;

    cudaFuncSetAttribute(knn_kernel, cudaFuncAttributeMaxDynamicSharedMemorySize, KNN_SMEM_BYTES);

    prep_kernel<<<192, 256>>>(w_lin, b_lin, w_aw, b_aw);
    xx_kernel<<<64, 256>>>(x);
    dummy_kernel<<<1, 32>>>();   // shifts knn into the ncu-captured launch slot
    knn_kernel<<<dim3(128, 4), 256, KNN_SMEM_BYTES>>>(x);
    gemmA_kernel<<<dim3(32, 4, 3), 256>>>(x);
    attn_kernel<<<dim3(4096, 4), 128>>>(x);
    gn_stats_kernel<<<16, 256>>>();
    prepw_kernel<<<4, 128>>>(conv_w, conv_b, gn_g, gn_b);
    gemmB_kernel<<<dim3(32, 4), 256>>>();
    bn_stats_kernel<<<1, 128>>>();
    final_kernel<<<8192, 256>>>(bn_g, bn_b, out);
}

// round 7
// speedup vs baseline: 1.4426x; 1.0003x over previous
#include <cuda_runtime.h>
#include <math.h>

#define NB 4
#define NC 128
#define NN 4096
#define NK 9

// ---------------- device scratch ----------------
__device__ __align__(16) float d_WT[128 * 384];     // [c][o] combined weights (P|Q|AW|pad)
__device__ float d_bias[384];
__device__ __align__(16) float d_xx[NB * NN];
__device__ int   d_knn_buf[NB * NN * NK];
__device__ __align__(16) float d_PQA[NB * NN * 384]; // [b][n][o]
__device__ __align__(16) float d_Y[NB * NN * 128];   // [b][n][c]
__device__ __align__(16) float d_Z[NB * 128 * NN];   // [b][o][n]
__device__ float d_gnp_s[16 * NN];
__device__ float d_gnp_q[16 * NN];
__device__ float d_gnm[16], d_gni[16];
__device__ __align__(16) float d_WPT[NB * 128 * 128]; // [b][c][o]
__device__ float d_E[NB * 128];
__device__ float d_bnp_s[128 * 128], d_bnp_q[128 * 128];
__device__ float d_bnm[128], d_bni[128];

// ---------------- f32x2 helpers ----------------
__device__ __forceinline__ unsigned long long pack2(float x, float y) {
    unsigned long long r;
    asm("mov.b64 %0, {%1, %2};" : "=l"(r) : "f"(x), "f"(y));
    return r;
}
__device__ __forceinline__ void fma2(unsigned long long& d, unsigned long long a, unsigned long long b) {
    asm("fma.rn.f32x2 %0, %1, %2, %0;" : "+l"(d) : "l"(a), "l"(b));
}
__device__ __forceinline__ float2 unpk(unsigned long long v) {
    float2 r;
    asm("mov.b64 {%0, %1}, %2;" : "=f"(r.x), "=f"(r.y) : "l"(v));
    return r;
}
__device__ __forceinline__ void cpasync16(void* dst, const void* src) {
    unsigned s = (unsigned)__cvta_generic_to_shared(dst);
    asm volatile("cp.async.cg.shared.global [%0], [%1], 16;" :: "r"(s), "l"(src) : "memory");
}
#define CP_COMMIT() asm volatile("cp.async.commit_group;" ::: "memory")
#define CP_WAIT0()  asm volatile("cp.async.wait_group 0;" ::: "memory")

// key: descending by value, ties -> smaller index first (matches lax.top_k)
__device__ __forceinline__ unsigned long long enckey(float v, int m) {
    unsigned u = __float_as_uint(v);
    unsigned mask = ((int)u < 0) ? 0xFFFFFFFFu : 0x80000000u;
    u ^= mask;
    return ((unsigned long long)u << 32) | (unsigned)(~m);
}

// ---------------- k0: combined weights (transposed) ----------------
__global__ void prep_kernel(const float* __restrict__ w_lin, const float* __restrict__ b_lin,
                            const float* __restrict__ w_aw, const float* __restrict__ b_aw) {
    int i = blockIdx.x * 256 + threadIdx.x;
    if (i >= 384 * 128) return;
    int o = i % 384, c = i / 384;
    float w = 0.f;
    if (o < 128)      w = w_lin[o * 256 + c] + w_lin[o * 256 + 128 + c];
    else if (o < 256) w = w_lin[(o - 128) * 256 + 128 + c];
    else if (o < 292) w = w_aw[(o - 256) * 128 + c];
    d_WT[c * 384 + o] = w;
    if (c == 0) {
        float bv = 0.f;
        if (o < 128) bv = b_lin[o];
        else if (o >= 256 && o < 292) bv = b_aw[o - 256];
        d_bias[o] = bv;
    }
}

// ---------------- k1: xx ----------------
__global__ void xx_kernel(const float* __restrict__ x) {
    int i = blockIdx.x * 256 + threadIdx.x;
    int b = i >> 12, n = i & (NN - 1);
    float s = 0.f;
    #pragma unroll 8
    for (int c = 0; c < 128; c++) {
        float v = x[(b * 128 + c) * NN + n];
        s = fmaf(v, v, s);
    }
    d_xx[i] = s;
}

// slot-shift dummy so knn lands in the ncu-captured launch position
__global__ void dummy_kernel() {}

// ---------------- k2: KNN ----------------
// Block: 32 query rows, 128 threads. Thread = (tr=tid>>4 -> 4 rows, tm=tid&15 -> 8 m).
// 4 rows/thread doubles FFMA2 per smem byte vs R5 (crossbar was 72% bound there).
// m-columns per thread: {tm*4..+3} and {64+tm*4..+3} (conflict-free LDS.128 phases).
// Dynamic smem layout (floats):
//   xnT  [128][36]        : 4608 floats
//   xmB  [2][16*132]      : 4224 floats
//   xxS  [2][128]         : 256 floats
//   lists[32*16*9] (u64)  : 4608 u64  (offset 9088 floats, 8B aligned)
#define KNN_SMEM_BYTES (9088 * 4 + 4608 * 8)

__global__ void __launch_bounds__(128) knn_kernel(const float* __restrict__ x) {
    extern __shared__ float sm[];
    float* xnT = sm;                                      // 4608
    float* xmB = sm + 4608;                               // 4224
    float* xxS = sm + 8832;                               // 256
    unsigned long long* lists = (unsigned long long*)(sm + 9088);

    const int b  = blockIdx.y;
    const int n0 = blockIdx.x * 32;
    const int tid = threadIdx.x;
    const int tr = tid >> 4, tm = tid & 15, r0 = tr * 4;
    const int ccL = tid >> 3;           // cp.async: channel within 16-ch chunk
    const int mlL = (tid & 7) * 16;     // cp.async: m offset (16 floats per thread)

    // init lists + load query tile (transposed: xnT[c][r])
    for (int i = tid; i < 4608; i += 128) lists[i] = 0ull;
    for (int i = tid; i < 4096; i += 128) {
        int c = i >> 5, r = i & 31;
        xnT[c * 36 + r] = x[(b * 128 + c) * NN + n0 + r];
    }

    unsigned long long th[4];
    unsigned long long* L[4];
    #pragma unroll
    for (int j = 0; j < 4; j++) {
        th[j] = 0ull;
        L[j] = lists + ((r0 + j) * 16 + tm) * 9;
    }

    // preload (mt=0, ck=0) + xx tile 0
    {
        const float* src = &x[(b * 128 + ccL) * NN + 0 + mlL];
        float* dst = xmB + ccL * 132 + mlL;
        cpasync16(dst, src);      cpasync16(dst + 4, src + 4);
        cpasync16(dst + 8, src + 8); cpasync16(dst + 12, src + 12);
        if (tid < 32) cpasync16(&xxS[tid * 4], &d_xx[b * NN + tid * 4]);
        CP_COMMIT();
    }

    for (int mt = 0; mt < 32; mt++) {
        const int m0 = mt * 128;
        unsigned long long acc[4][4];
        #pragma unroll
        for (int j = 0; j < 4; j++)
            #pragma unroll
            for (int i = 0; i < 4; i++) acc[j][i] = 0ull;

        for (int ck = 0; ck < 8; ck++) {
            CP_WAIT0();
            __syncthreads();
            // issue next prefetch (other buffer; safe after the barrier)
            if (ck < 7) {
                const float* src = &x[(b * 128 + (ck + 1) * 16 + ccL) * NN + m0 + mlL];
                float* dst = xmB + ((ck + 1) & 1) * 2112 + ccL * 132 + mlL;
                cpasync16(dst, src);      cpasync16(dst + 4, src + 4);
                cpasync16(dst + 8, src + 8); cpasync16(dst + 12, src + 12);
                CP_COMMIT();
            } else if (mt < 31) {
                const int m0n = m0 + 128;
                const float* src = &x[(b * 128 + ccL) * NN + m0n + mlL];
                float* dst = xmB + ccL * 132 + mlL;   // ck=0 -> buffer 0
                cpasync16(dst, src);      cpasync16(dst + 4, src + 4);
                cpasync16(dst + 8, src + 8); cpasync16(dst + 12, src + 12);
                if (tid < 32) cpasync16(&xxS[((mt + 1) & 1) * 128 + tid * 4],
                                        &d_xx[b * NN + m0n + tid * 4]);
                CP_COMMIT();
            }
            const float* xb = xmB + (ck & 1) * 2112;
            #pragma unroll
            for (int cc = 0; cc < 16; cc++) {
                const float4 av = *(const float4*)(xnT + (ck * 16 + cc) * 36 + r0);
                ulonglong2 c0 = *(const ulonglong2*)(const void*)(xb + cc * 132 + tm * 4);
                ulonglong2 c1 = *(const ulonglong2*)(const void*)(xb + cc * 132 + 64 + tm * 4);
                unsigned long long ad;
                ad = pack2(av.x, av.x);
                fma2(acc[0][0], ad, c0.x); fma2(acc[0][1], ad, c0.y);
                fma2(acc[0][2], ad, c1.x); fma2(acc[0][3], ad, c1.y);
                ad = pack2(av.y, av.y);
                fma2(acc[1][0], ad, c0.x); fma2(acc[1][1], ad, c0.y);
                fma2(acc[1][2], ad, c1.x); fma2(acc[1][3], ad, c1.y);
                ad = pack2(av.z, av.z);
                fma2(acc[2][0], ad, c0.x); fma2(acc[2][1], ad, c0.y);
                fma2(acc[2][2], ad, c1.x); fma2(acc[2][3], ad, c1.y);
                ad = pack2(av.w, av.w);
                fma2(acc[3][0], ad, c0.x); fma2(acc[3][1], ad, c0.y);
                fma2(acc[3][2], ad, c1.x); fma2(acc[3][3], ad, c1.y);
            }
        }

        // selection: cols map to m = m0+tm*4+{0..3} and m0+64+tm*4+{0..3}
        const float* xp = xxS + (mt & 1) * 128;
        float4 q0 = *(const float4*)(xp + tm * 4);
        float4 q1 = *(const float4*)(xp + 64 + tm * 4);
        float xx8[8] = {q0.x, q0.y, q0.z, q0.w, q1.x, q1.y, q1.z, q1.w};
        int mb[8];
        #pragma unroll
        for (int j = 0; j < 4; j++) { mb[j] = m0 + tm * 4 + j; mb[4 + j] = m0 + 64 + tm * 4 + j; }
        #pragma unroll
        for (int j = 0; j < 4; j++) {
            float2 p0 = unpk(acc[j][0]), p1 = unpk(acc[j][1]);
            float2 p2 = unpk(acc[j][2]), p3 = unpk(acc[j][3]);
            float vv[8] = {p0.x, p0.y, p1.x, p1.y, p2.x, p2.y, p3.x, p3.y};
            unsigned long long* Lj = L[j];
            #pragma unroll
            for (int i = 0; i < 8; i++) {
                unsigned long long key = enckey(2.f * vv[i] - xx8[i], mb[i]);
                if (key > th[j]) {
                    #pragma unroll
                    for (int q = 0; q < 9; q++) {
                        unsigned long long cur = Lj[q];
                        if (key > cur) { Lj[q] = key; key = cur; }
                    }
                    th[j] = Lj[8];
                }
            }
        }
    }

    // merge 16 sorted lists per row
    __syncthreads();
    if (tid < 32) {
        const unsigned long long* base = lists + tid * 144;
        int h[16];
        #pragma unroll
        for (int l = 0; l < 16; l++) h[l] = 0;
        for (int q = 0; q < 9; q++) {
            unsigned long long best = 0; int bl = 0;
            #pragma unroll
            for (int l = 0; l < 16; l++) {
                if (h[l] < 9) {
                    unsigned long long kk = base[l * 9 + h[l]];
                    if (kk > best) { best = kk; bl = l; }
                }
            }
            h[bl]++;
            d_knn_buf[(b * NN + n0 + tid) * NK + q] = (int)(~(unsigned)best);
        }
    }
}

// ---------------- k3: GEMM A  out[b][n][o] = sum_c WT[c][o]*x[b][c][n] + bias ----------------
__global__ void __launch_bounds__(256) gemmA_kernel(const float* __restrict__ x) {
    int b = blockIdx.y, n0 = blockIdx.x * 128, o0 = blockIdx.z * 128;
    __shared__ __align__(16) float Ws[32 * 132];
    __shared__ __align__(16) float Xs[32 * 132];
    int tx = threadIdx.x & 15, ty = threadIdx.x >> 4;
    float acc[8][8];
    {
        float bias[8];
        #pragma unroll
        for (int i = 0; i < 8; i++) bias[i] = d_bias[o0 + ty * 8 + i];
        #pragma unroll
        for (int j = 0; j < 8; j++)
            #pragma unroll
            for (int i = 0; i < 8; i++) acc[j][i] = bias[i];
    }
    for (int c0 = 0; c0 < 128; c0 += 32) {
        __syncthreads();
        for (int t = threadIdx.x; t < 32 * 128; t += 256) {
            int cc = t >> 7, oo = t & 127;
            Ws[cc * 132 + oo] = d_WT[(c0 + cc) * 384 + o0 + oo];
            Xs[cc * 132 + oo] = x[(b * 128 + c0 + cc) * NN + n0 + oo];
        }
        __syncthreads();
        #pragma unroll
        for (int cc = 0; cc < 32; cc++) {
            float4 w0 = *(const float4*)(Ws + cc * 132 + ty * 8);
            float4 w1 = *(const float4*)(Ws + cc * 132 + ty * 8 + 4);
            #pragma unroll
            for (int j = 0; j < 8; j++) {
                float xv = Xs[cc * 132 + tx + 16 * j];
                acc[j][0] = fmaf(w0.x, xv, acc[j][0]);
                acc[j][1] = fmaf(w0.y, xv, acc[j][1]);
                acc[j][2] = fmaf(w0.z, xv, acc[j][2]);
                acc[j][3] = fmaf(w0.w, xv, acc[j][3]);
                acc[j][4] = fmaf(w1.x, xv, acc[j][4]);
                acc[j][5] = fmaf(w1.y, xv, acc[j][5]);
                acc[j][6] = fmaf(w1.z, xv, acc[j][6]);
                acc[j][7] = fmaf(w1.w, xv, acc[j][7]);
            }
        }
    }
    #pragma unroll
    for (int j = 0; j < 8; j++) {
        int n = n0 + tx + 16 * j;
        float* dp = d_PQA + (b * NN + n) * 384 + o0 + ty * 8;
        *(float4*)dp       = make_float4(acc[j][0], acc[j][1], acc[j][2], acc[j][3]);
        *(float4*)(dp + 4) = make_float4(acc[j][4], acc[j][5], acc[j][6], acc[j][7]);
    }
}

// ---------------- k4: per-point attention ----------------
__global__ void __launch_bounds__(128) attn_kernel(const float* __restrict__ x) {
    int n = blockIdx.x, b = blockIdx.y;
    int c = threadIdx.x, g = c >> 5;
    __shared__ float fS[9 * 132];
    __shared__ float sS[4 * 81];
    __shared__ float awS[36], tS[36];
    __shared__ int idxS[9];
    int base = (b * NN + n) * 384;
    if (c < 9)  idxS[c] = d_knn_buf[(b * NN + n) * NK + c];
    if (c < 36) awS[c] = d_PQA[base + 256 + c];
    __syncthreads();
    float P = d_PQA[base + c];
    float e9[9];
    #pragma unroll
    for (int k = 0; k < 9; k++) {
        float f = P - d_PQA[(b * NN + idxS[k]) * 384 + 128 + c];
        fS[k * 132 + c] = f;
        e9[k] = f > 0.f ? f : expm1f(f);
    }
    if (c < 4) {
        float* row = awS + c * 9;
        float mx = row[0];
        #pragma unroll
        for (int k = 1; k < 9; k++) mx = fmaxf(mx, row[k]);
        float sm = 0.f;
        #pragma unroll
        for (int k = 0; k < 9; k++) { float e = expf(row[k] - mx); row[k] = e; sm += e; }
        float inv = 1.f / sm;
        #pragma unroll
        for (int k = 0; k < 9; k++) row[k] *= inv;
    }
    __syncthreads();
    for (int t = c; t < 324; t += 128) {
        int g2 = t / 81, p = t % 81, k = p / 9, j = p % 9;
        const float* fa = fS + k * 132 + g2 * 32;
        const float* fb = fS + j * 132 + g2 * 32;
        float s = 0.f;
        #pragma unroll
        for (int q = 0; q < 32; q++) s = fmaf(fa[q], fb[q], s);
        sS[g2 * 81 + p] = s * 0.17677669529663689f;
    }
    __syncthreads();
    if (c < 36) {
        float* row = sS + (c / 9) * 81 + (c % 9) * 9;
        float mx = row[0];
        #pragma unroll
        for (int j = 1; j < 9; j++) mx = fmaxf(mx, row[j]);
        float sm = 0.f;
        #pragma unroll
        for (int j = 0; j < 9; j++) { float e = expf(row[j] - mx); row[j] = e; sm += e; }
        float inv = 1.f / sm;
        #pragma unroll
        for (int j = 0; j < 9; j++) row[j] *= inv;
    }
    __syncthreads();
    if (c < 36) {
        int g2 = c / 9, j = c % 9;
        float tv = 0.f;
        #pragma unroll
        for (int k = 0; k < 9; k++) tv = fmaf(awS[g2 * 9 + k], sS[g2 * 81 + k * 9 + j], tv);
        tS[c] = tv;
    }
    __syncthreads();
    float lf = 0.f;
    #pragma unroll
    for (int j = 0; j < 9; j++) lf = fmaf(tS[g * 9 + j], e9[j], lf);
    float yv = lf + x[(b * 128 + c) * NN + n];
    d_Y[(b * NN + n) * 128 + c] = yv;
    float s1 = yv, s2 = yv * yv;
    #pragma unroll
    for (int off = 16; off; off >>= 1) {
        s1 += __shfl_xor_sync(0xffffffffu, s1, off);
        s2 += __shfl_xor_sync(0xffffffffu, s2, off);
    }
    if ((c & 31) == 0) {
        d_gnp_s[(b * 4 + g) * NN + n] = s1;
        d_gnp_q[(b * 4 + g) * NN + n] = s2;
    }
}

// ---------------- k5: GN stats (deterministic) ----------------
__global__ void gn_stats_kernel() {
    int bg = blockIdx.x;
    __shared__ double sh[256], sh2[256];
    double s = 0.0, q = 0.0;
    for (int i = threadIdx.x; i < NN; i += 256) {
        s += (double)d_gnp_s[bg * NN + i];
        q += (double)d_gnp_q[bg * NN + i];
    }
    sh[threadIdx.x] = s; sh2[threadIdx.x] = q;
    __syncthreads();
    for (int off = 128; off; off >>= 1) {
        if (threadIdx.x < off) { sh[threadIdx.x] += sh[threadIdx.x + off]; sh2[threadIdx.x] += sh2[threadIdx.x + off]; }
        __syncthreads();
    }
    if (threadIdx.x == 0) {
        double cnt = 32.0 * NN;
        double mean = sh[0] / cnt;
        double var = sh2[0] / cnt - mean * mean;
        d_gnm[bg] = (float)mean;
        d_gni[bg] = (float)(1.0 / sqrt(var + 1e-5));
    }
}

// ---------------- k6: fold GN into conv weights ----------------
__global__ void prepw_kernel(const float* __restrict__ conv_w, const float* __restrict__ conv_b,
                             const float* __restrict__ gn_g, const float* __restrict__ gn_b) {
    int b = blockIdx.x, o = threadIdx.x;
    float e = conv_b[o];
    for (int c = 0; c < 128; c++) {
        int g = c >> 5;
        float inv = d_gni[b * 4 + g];
        float A = gn_g[c] * inv;
        float D = gn_b[c] - d_gnm[b * 4 + g] * A;
        float w = conv_w[o * 128 + c];
        e = fmaf(w, D, e);
        d_WPT[(b * 128 + c) * 128 + o] = w * A;
    }
    d_E[b * 128 + o] = e;
}

// ---------------- k7: GEMM B  z[b][o][n] = sum_c WPT[b][c][o]*Y[b][n][c] + E ----------------
__global__ void __launch_bounds__(256) gemmB_kernel() {
    int b = blockIdx.y, n0 = blockIdx.x * 128;
    __shared__ __align__(16) float Ws[32 * 132];
    __shared__ __align__(16) float Ys[128 * 33];
    int tx = threadIdx.x & 15, ty = threadIdx.x >> 4;
    float acc[8][8];
    {
        float eb[8];
        #pragma unroll
        for (int i = 0; i < 8; i++) eb[i] = d_E[b * 128 + ty * 8 + i];
        #pragma unroll
        for (int j = 0; j < 8; j++)
            #pragma unroll
            for (int i = 0; i < 8; i++) acc[j][i] = eb[i];
    }
    for (int c0 = 0; c0 < 128; c0 += 32) {
        __syncthreads();
        for (int t = threadIdx.x; t < 32 * 128; t += 256) {
            int cc = t >> 7, oo = t & 127;
            Ws[cc * 132 + oo] = d_WPT[(b * 128 + c0 + cc) * 128 + oo];
            int nl = t >> 5, cl = t & 31;
            Ys[nl * 33 + cl] = d_Y[(b * NN + n0 + nl) * 128 + c0 + cl];
        }
        __syncthreads();
        #pragma unroll
        for (int cc = 0; cc < 32; cc++) {
            float4 w0 = *(const float4*)(Ws + cc * 132 + ty * 8);
            float4 w1 = *(const float4*)(Ws + cc * 132 + ty * 8 + 4);
            #pragma unroll
            for (int j = 0; j < 8; j++) {
                float yv = Ys[(tx + 16 * j) * 33 + cc];
                acc[j][0] = fmaf(w0.x, yv, acc[j][0]);
                acc[j][1] = fmaf(w0.y, yv, acc[j][1]);
                acc[j][2] = fmaf(w0.z, yv, acc[j][2]);
                acc[j][3] = fmaf(w0.w, yv, acc[j][3]);
                acc[j][4] = fmaf(w1.x, yv, acc[j][4]);
                acc[j][5] = fmaf(w1.y, yv, acc[j][5]);
                acc[j][6] = fmaf(w1.z, yv, acc[j][6]);
                acc[j][7] = fmaf(w1.w, yv, acc[j][7]);
            }
        }
    }
    #pragma unroll
    for (int j = 0; j < 8; j++) {
        int n = n0 + tx + 16 * j;
        #pragma unroll
        for (int i = 0; i < 8; i++)
            d_Z[(b * 128 + ty * 8 + i) * NN + n] = acc[j][i];
    }
    // deterministic per-block BN partials
    float* red = Ys;
    __syncthreads();
    #pragma unroll
    for (int i = 0; i < 8; i++) {
        float s = 0.f, q = 0.f;
        #pragma unroll
        for (int j = 0; j < 8; j++) { s += acc[j][i]; q = fmaf(acc[j][i], acc[j][i], q); }
        red[(ty * 8 + i) * 16 + tx] = s;
        red[2048 + (ty * 8 + i) * 16 + tx] = q;
    }
    __syncthreads();
    if (threadIdx.x < 128) {
        int o = threadIdx.x;
        float s = 0.f, q = 0.f;
        #pragma unroll
        for (int t = 0; t < 16; t++) { s += red[o * 16 + t]; q += red[2048 + o * 16 + t]; }
        int blk = blockIdx.y * 32 + blockIdx.x;
        d_bnp_s[o * 128 + blk] = s;
        d_bnp_q[o * 128 + blk] = q;
    }
}

// ---------------- k8: BN stats ----------------
__global__ void bn_stats_kernel() {
    int o = threadIdx.x;
    double s = 0.0, q = 0.0;
    for (int k = 0; k < 128; k++) { s += (double)d_bnp_s[o * 128 + k]; q += (double)d_bnp_q[o * 128 + k]; }
    double cnt = (double)(NB * NN);
    double mean = s / cnt;
    double var = q / cnt - mean * mean;
    d_bnm[o] = (float)mean;
    d_bni[o] = (float)(1.0 / sqrt(var + 1e-5));
}

// ---------------- k9: BN apply + relu ----------------
__global__ void final_kernel(const float* __restrict__ bn_g, const float* __restrict__ bn_b,
                             float* __restrict__ out) {
    int i = blockIdx.x * 256 + threadIdx.x;
    int o = (i >> 12) & 127;
    float v = (d_Z[i] - d_bnm[o]) * d_bni[o] * bn_g[o] + bn_b[o];
    out[i] = fmaxf(v, 0.f);
}

extern "C" void kernel_launch(void* const* d_in, const int* in_sizes, int n_in,
                              void* d_out, int out_size) {
    const float* x      = (const float*)d_in[0];
    const float* w_lin  = (const float*)d_in[1];
    const float* b_lin  = (const float*)d_in[2];
    const float* w_aw   = (const float*)d_in[3];
    const float* b_aw   = (const float*)d_in[4];
    const float* gn_g   = (const float*)d_in[5];
    const float* gn_b   = (const float*)d_in[6];
    const float* conv_w = (const float*)d_in[7];
    const float* conv_b = (const float*)d_in[8];
    const float* bn_g   = (const float*)d_in[9];
    const float* bn_b   = (const float*)d_in[10];
    float* out = (float*)d_out;

    cudaFuncSetAttribute(knn_kernel, cudaFuncAttributeMaxDynamicSharedMemorySize, KNN_SMEM_BYTES);

    prep_kernel<<<192, 256>>>(w_lin, b_lin, w_aw, b_aw);
    xx_kernel<<<64, 256>>>(x);
    dummy_kernel<<<1, 32>>>();   // keeps knn in the ncu-captured launch slot
    knn_kernel<<<dim3(128, 4), 128, KNN_SMEM_BYTES>>>(x);
    gemmA_kernel<<<dim3(32, 4, 3), 256>>>(x);
    attn_kernel<<<dim3(4096, 4), 128>>>(x);
    gn_stats_kernel<<<16, 256>>>();
    prepw_kernel<<<4, 128>>>(conv_w, conv_b, gn_g, gn_b);
    gemmB_kernel<<<dim3(32, 4), 256>>>();
    bn_stats_kernel<<<1, 128>>>();
    final_kernel<<<8192, 256>>>(bn_g, bn_b, out);
}

// round 8
// speedup vs baseline: 1.5136x; 1.0492x over previous
#include <cuda_runtime.h>
#include <math.h>

#define NB 4
#define NC 128
#define NN 4096
#define NK 9

// ---------------- device scratch ----------------
__device__ __align__(16) float d_WT[128 * 384];     // [c][o] combined weights (P|Q|AW|pad)
__device__ float d_bias[384];
__device__ __align__(16) float d_xx[NB * NN];
__device__ int   d_knn_buf[NB * NN * NK];
__device__ __align__(16) float d_PQA[NB * NN * 384]; // [b][n][o]
__device__ __align__(16) float d_Y[NB * NN * 128];   // [b][n][c]
__device__ __align__(16) float d_Z[NB * 128 * NN];   // [b][o][n]
__device__ float d_gnp_s[16 * NN];
__device__ float d_gnp_q[16 * NN];
__device__ float d_gnm[16], d_gni[16];
__device__ __align__(16) float d_WPT[NB * 128 * 128]; // [b][c][o]
__device__ float d_E[NB * 128];
__device__ float d_bnp_s[128 * 128], d_bnp_q[128 * 128];
__device__ float d_bnm[128], d_bni[128];

// ---------------- f32x2 helpers ----------------
__device__ __forceinline__ unsigned long long pack2(float x, float y) {
    unsigned long long r;
    asm("mov.b64 %0, {%1, %2};" : "=l"(r) : "f"(x), "f"(y));
    return r;
}
__device__ __forceinline__ void fma2(unsigned long long& d, unsigned long long a, unsigned long long b) {
    asm("fma.rn.f32x2 %0, %1, %2, %0;" : "+l"(d) : "l"(a), "l"(b));
}
__device__ __forceinline__ float2 unpk(unsigned long long v) {
    float2 r;
    asm("mov.b64 {%0, %1}, %2;" : "=f"(r.x), "=f"(r.y) : "l"(v));
    return r;
}
__device__ __forceinline__ void cpasync16(void* dst, const void* src) {
    unsigned s = (unsigned)__cvta_generic_to_shared(dst);
    asm volatile("cp.async.cg.shared.global [%0], [%1], 16;" :: "r"(s), "l"(src) : "memory");
}
#define CP_COMMIT() asm volatile("cp.async.commit_group;" ::: "memory")
#define CP_WAIT0()  asm volatile("cp.async.wait_group 0;" ::: "memory")

// key: descending by value, ties -> smaller index first (matches lax.top_k)
__device__ __forceinline__ unsigned long long enckey(float v, int m) {
    unsigned u = __float_as_uint(v);
    unsigned mask = ((int)u < 0) ? 0xFFFFFFFFu : 0x80000000u;
    u ^= mask;
    return ((unsigned long long)u << 32) | (unsigned)(~m);
}

// ---------------- k0: combined weights (transposed) ----------------
__global__ void prep_kernel(const float* __restrict__ w_lin, const float* __restrict__ b_lin,
                            const float* __restrict__ w_aw, const float* __restrict__ b_aw) {
    int i = blockIdx.x * 256 + threadIdx.x;
    if (i >= 384 * 128) return;
    int o = i % 384, c = i / 384;
    float w = 0.f;
    if (o < 128)      w = w_lin[o * 256 + c] + w_lin[o * 256 + 128 + c];
    else if (o < 256) w = w_lin[(o - 128) * 256 + 128 + c];
    else if (o < 292) w = w_aw[(o - 256) * 128 + c];
    d_WT[c * 384 + o] = w;
    if (c == 0) {
        float bv = 0.f;
        if (o < 128) bv = b_lin[o];
        else if (o >= 256 && o < 292) bv = b_aw[o - 256];
        d_bias[o] = bv;
    }
}

// ---------------- k1: xx ----------------
__global__ void xx_kernel(const float* __restrict__ x) {
    int i = blockIdx.x * 256 + threadIdx.x;
    int b = i >> 12, n = i & (NN - 1);
    float s = 0.f;
    #pragma unroll 8
    for (int c = 0; c < 128; c++) {
        float v = x[(b * 128 + c) * NN + n];
        s = fmaf(v, v, s);
    }
    d_xx[i] = s;
}

// slot-shift dummy so knn lands in the ncu-captured launch position
__global__ void dummy_kernel() {}

// ---------------- k2: KNN ----------------
// Block: 32 query rows, 128 threads. Thread = (tr=tid>>4 -> 4 rows, tm=tid&15 -> 8 m).
// R7: the cc loop is explicitly software-pipelined -- cc+1's A/B operands are
// loaded into registers before cc's 16 FFMA2s issue, giving every LDS ~32
// issue-slots of independent cover (R5/R6 were latency-bound on the serial
// LDS->MOV->FFMA2 chain: fma pinned ~31%, issue ~41%, occupancy-invariant).
// Dynamic smem layout (floats):
//   xnT  [128][36]        : 4608 floats
//   xmB  [2][16*132]      : 4224 floats
//   xxS  [2][128]         : 256 floats
//   lists[32*16*9] (u64)  : 4608 u64  (offset 9088 floats, 8B aligned)
#define KNN_SMEM_BYTES (9088 * 4 + 4608 * 8)

__global__ void __launch_bounds__(128) knn_kernel(const float* __restrict__ x) {
    extern __shared__ float sm[];
    float* xnT = sm;                                      // 4608
    float* xmB = sm + 4608;                               // 4224
    float* xxS = sm + 8832;                               // 256
    unsigned long long* lists = (unsigned long long*)(sm + 9088);

    const int b  = blockIdx.y;
    const int n0 = blockIdx.x * 32;
    const int tid = threadIdx.x;
    const int tr = tid >> 4, tm = tid & 15, r0 = tr * 4;
    const int ccL = tid >> 3;           // cp.async: channel within 16-ch chunk
    const int mlL = (tid & 7) * 16;     // cp.async: m offset (16 floats per thread)

    // init lists + load query tile (transposed: xnT[c][r])
    for (int i = tid; i < 4608; i += 128) lists[i] = 0ull;
    for (int i = tid; i < 4096; i += 128) {
        int c = i >> 5, r = i & 31;
        xnT[c * 36 + r] = x[(b * 128 + c) * NN + n0 + r];
    }

    unsigned long long th[4];
    unsigned long long* L[4];
    #pragma unroll
    for (int j = 0; j < 4; j++) {
        th[j] = 0ull;
        L[j] = lists + ((r0 + j) * 16 + tm) * 9;
    }

    // preload (mt=0, ck=0) + xx tile 0
    {
        const float* src = &x[(b * 128 + ccL) * NN + 0 + mlL];
        float* dst = xmB + ccL * 132 + mlL;
        cpasync16(dst, src);      cpasync16(dst + 4, src + 4);
        cpasync16(dst + 8, src + 8); cpasync16(dst + 12, src + 12);
        if (tid < 32) cpasync16(&xxS[tid * 4], &d_xx[b * NN + tid * 4]);
        CP_COMMIT();
    }

    for (int mt = 0; mt < 32; mt++) {
        const int m0 = mt * 128;
        unsigned long long acc[4][4];
        #pragma unroll
        for (int j = 0; j < 4; j++)
            #pragma unroll
            for (int i = 0; i < 4; i++) acc[j][i] = 0ull;

        for (int ck = 0; ck < 8; ck++) {
            CP_WAIT0();
            __syncthreads();
            // issue next prefetch (other buffer; safe after the barrier)
            if (ck < 7) {
                const float* src = &x[(b * 128 + (ck + 1) * 16 + ccL) * NN + m0 + mlL];
                float* dst = xmB + ((ck + 1) & 1) * 2112 + ccL * 132 + mlL;
                cpasync16(dst, src);      cpasync16(dst + 4, src + 4);
                cpasync16(dst + 8, src + 8); cpasync16(dst + 12, src + 12);
                CP_COMMIT();
            } else if (mt < 31) {
                const int m0n = m0 + 128;
                const float* src = &x[(b * 128 + ccL) * NN + m0n + mlL];
                float* dst = xmB + ccL * 132 + mlL;   // ck=0 -> buffer 0
                cpasync16(dst, src);      cpasync16(dst + 4, src + 4);
                cpasync16(dst + 8, src + 8); cpasync16(dst + 12, src + 12);
                if (tid < 32) cpasync16(&xxS[((mt + 1) & 1) * 128 + tid * 4],
                                        &d_xx[b * NN + m0n + tid * 4]);
                CP_COMMIT();
            }
            const float* xb = xmB + (ck & 1) * 2112;
            const float* xa = xnT + (ck * 16) * 36 + r0;

            // software-pipelined cc loop: load cc+1 before cc's FFMA2 block
            float4 av = *(const float4*)xa;
            ulonglong2 c0 = *(const ulonglong2*)(const void*)(xb + tm * 4);
            ulonglong2 c1 = *(const ulonglong2*)(const void*)(xb + 64 + tm * 4);
            #pragma unroll
            for (int cc = 0; cc < 16; cc++) {
                float4 avn;
                ulonglong2 c0n, c1n;
                if (cc < 15) {
                    avn = *(const float4*)(xa + (cc + 1) * 36);
                    c0n = *(const ulonglong2*)(const void*)(xb + (cc + 1) * 132 + tm * 4);
                    c1n = *(const ulonglong2*)(const void*)(xb + (cc + 1) * 132 + 64 + tm * 4);
                } else {
                    avn = av; c0n = c0; c1n = c1;
                }
                unsigned long long ad;
                ad = pack2(av.x, av.x);
                fma2(acc[0][0], ad, c0.x); fma2(acc[0][1], ad, c0.y);
                fma2(acc[0][2], ad, c1.x); fma2(acc[0][3], ad, c1.y);
                ad = pack2(av.y, av.y);
                fma2(acc[1][0], ad, c0.x); fma2(acc[1][1], ad, c0.y);
                fma2(acc[1][2], ad, c1.x); fma2(acc[1][3], ad, c1.y);
                ad = pack2(av.z, av.z);
                fma2(acc[2][0], ad, c0.x); fma2(acc[2][1], ad, c0.y);
                fma2(acc[2][2], ad, c1.x); fma2(acc[2][3], ad, c1.y);
                ad = pack2(av.w, av.w);
                fma2(acc[3][0], ad, c0.x); fma2(acc[3][1], ad, c0.y);
                fma2(acc[3][2], ad, c1.x); fma2(acc[3][3], ad, c1.y);
                av = avn; c0 = c0n; c1 = c1n;
            }
        }

        // selection: cols map to m = m0+tm*4+{0..3} and m0+64+tm*4+{0..3}
        const float* xp = xxS + (mt & 1) * 128;
        float4 q0 = *(const float4*)(xp + tm * 4);
        float4 q1 = *(const float4*)(xp + 64 + tm * 4);
        float xx8[8] = {q0.x, q0.y, q0.z, q0.w, q1.x, q1.y, q1.z, q1.w};
        int mb[8];
        #pragma unroll
        for (int j = 0; j < 4; j++) { mb[j] = m0 + tm * 4 + j; mb[4 + j] = m0 + 64 + tm * 4 + j; }
        #pragma unroll
        for (int j = 0; j < 4; j++) {
            float2 p0 = unpk(acc[j][0]), p1 = unpk(acc[j][1]);
            float2 p2 = unpk(acc[j][2]), p3 = unpk(acc[j][3]);
            float vv[8] = {p0.x, p0.y, p1.x, p1.y, p2.x, p2.y, p3.x, p3.y};
            unsigned long long* Lj = L[j];
            #pragma unroll
            for (int i = 0; i < 8; i++) {
                unsigned long long key = enckey(2.f * vv[i] - xx8[i], mb[i]);
                if (key > th[j]) {
                    #pragma unroll
                    for (int q = 0; q < 9; q++) {
                        unsigned long long cur = Lj[q];
                        if (key > cur) { Lj[q] = key; key = cur; }
                    }
                    th[j] = Lj[8];
                }
            }
        }
    }

    // merge 16 sorted lists per row
    __syncthreads();
    if (tid < 32) {
        const unsigned long long* base = lists + tid * 144;
        int h[16];
        #pragma unroll
        for (int l = 0; l < 16; l++) h[l] = 0;
        for (int q = 0; q < 9; q++) {
            unsigned long long best = 0; int bl = 0;
            #pragma unroll
            for (int l = 0; l < 16; l++) {
                if (h[l] < 9) {
                    unsigned long long kk = base[l * 9 + h[l]];
                    if (kk > best) { best = kk; bl = l; }
                }
            }
            h[bl]++;
            d_knn_buf[(b * NN + n0 + tid) * NK + q] = (int)(~(unsigned)best);
        }
    }
}

// ---------------- k3: GEMM A  out[b][n][o] = sum_c WT[c][o]*x[b][c][n] + bias ----------------
__global__ void __launch_bounds__(256) gemmA_kernel(const float* __restrict__ x) {
    int b = blockIdx.y, n0 = blockIdx.x * 128, o0 = blockIdx.z * 128;
    __shared__ __align__(16) float Ws[32 * 132];
    __shared__ __align__(16) float Xs[32 * 132];
    int tx = threadIdx.x & 15, ty = threadIdx.x >> 4;
    float acc[8][8];
    {
        float bias[8];
        #pragma unroll
        for (int i = 0; i < 8; i++) bias[i] = d_bias[o0 + ty * 8 + i];
        #pragma unroll
        for (int j = 0; j < 8; j++)
            #pragma unroll
            for (int i = 0; i < 8; i++) acc[j][i] = bias[i];
    }
    for (int c0 = 0; c0 < 128; c0 += 32) {
        __syncthreads();
        for (int t = threadIdx.x; t < 32 * 128; t += 256) {
            int cc = t >> 7, oo = t & 127;
            Ws[cc * 132 + oo] = d_WT[(c0 + cc) * 384 + o0 + oo];
            Xs[cc * 132 + oo] = x[(b * 128 + c0 + cc) * NN + n0 + oo];
        }
        __syncthreads();
        #pragma unroll
        for (int cc = 0; cc < 32; cc++) {
            float4 w0 = *(const float4*)(Ws + cc * 132 + ty * 8);
            float4 w1 = *(const float4*)(Ws + cc * 132 + ty * 8 + 4);
            #pragma unroll
            for (int j = 0; j < 8; j++) {
                float xv = Xs[cc * 132 + tx + 16 * j];
                acc[j][0] = fmaf(w0.x, xv, acc[j][0]);
                acc[j][1] = fmaf(w0.y, xv, acc[j][1]);
                acc[j][2] = fmaf(w0.z, xv, acc[j][2]);
                acc[j][3] = fmaf(w0.w, xv, acc[j][3]);
                acc[j][4] = fmaf(w1.x, xv, acc[j][4]);
                acc[j][5] = fmaf(w1.y, xv, acc[j][5]);
                acc[j][6] = fmaf(w1.z, xv, acc[j][6]);
                acc[j][7] = fmaf(w1.w, xv, acc[j][7]);
            }
        }
    }
    #pragma unroll
    for (int j = 0; j < 8; j++) {
        int n = n0 + tx + 16 * j;
        float* dp = d_PQA + (b * NN + n) * 384 + o0 + ty * 8;
        *(float4*)dp       = make_float4(acc[j][0], acc[j][1], acc[j][2], acc[j][3]);
        *(float4*)(dp + 4) = make_float4(acc[j][4], acc[j][5], acc[j][6], acc[j][7]);
    }
}

// ---------------- k4: per-point attention ----------------
__global__ void __launch_bounds__(128) attn_kernel(const float* __restrict__ x) {
    int n = blockIdx.x, b = blockIdx.y;
    int c = threadIdx.x, g = c >> 5;
    __shared__ float fS[9 * 132];
    __shared__ float sS[4 * 81];
    __shared__ float awS[36], tS[36];
    __shared__ int idxS[9];
    int base = (b * NN + n) * 384;
    if (c < 9)  idxS[c] = d_knn_buf[(b * NN + n) * NK + c];
    if (c < 36) awS[c] = d_PQA[base + 256 + c];
    __syncthreads();
    float P = d_PQA[base + c];
    float e9[9];
    #pragma unroll
    for (int k = 0; k < 9; k++) {
        float f = P - d_PQA[(b * NN + idxS[k]) * 384 + 128 + c];
        fS[k * 132 + c] = f;
        e9[k] = f > 0.f ? f : expm1f(f);
    }
    if (c < 4) {
        float* row = awS + c * 9;
        float mx = row[0];
        #pragma unroll
        for (int k = 1; k < 9; k++) mx = fmaxf(mx, row[k]);
        float sm = 0.f;
        #pragma unroll
        for (int k = 0; k < 9; k++) { float e = expf(row[k] - mx); row[k] = e; sm += e; }
        float inv = 1.f / sm;
        #pragma unroll
        for (int k = 0; k < 9; k++) row[k] *= inv;
    }
    __syncthreads();
    for (int t = c; t < 324; t += 128) {
        int g2 = t / 81, p = t % 81, k = p / 9, j = p % 9;
        const float* fa = fS + k * 132 + g2 * 32;
        const float* fb = fS + j * 132 + g2 * 32;
        float s = 0.f;
        #pragma unroll
        for (int q = 0; q < 32; q++) s = fmaf(fa[q], fb[q], s);
        sS[g2 * 81 + p] = s * 0.17677669529663689f;
    }
    __syncthreads();
    if (c < 36) {
        float* row = sS + (c / 9) * 81 + (c % 9) * 9;
        float mx = row[0];
        #pragma unroll
        for (int j = 1; j < 9; j++) mx = fmaxf(mx, row[j]);
        float sm = 0.f;
        #pragma unroll
        for (int j = 0; j < 9; j++) { float e = expf(row[j] - mx); row[j] = e; sm += e; }
        float inv = 1.f / sm;
        #pragma unroll
        for (int j = 0; j < 9; j++) row[j] *= inv;
    }
    __syncthreads();
    if (c < 36) {
        int g2 = c / 9, j = c % 9;
        float tv = 0.f;
        #pragma unroll
        for (int k = 0; k < 9; k++) tv = fmaf(awS[g2 * 9 + k], sS[g2 * 81 + k * 9 + j], tv);
        tS[c] = tv;
    }
    __syncthreads();
    float lf = 0.f;
    #pragma unroll
    for (int j = 0; j < 9; j++) lf = fmaf(tS[g * 9 + j], e9[j], lf);
    float yv = lf + x[(b * 128 + c) * NN + n];
    d_Y[(b * NN + n) * 128 + c] = yv;
    float s1 = yv, s2 = yv * yv;
    #pragma unroll
    for (int off = 16; off; off >>= 1) {
        s1 += __shfl_xor_sync(0xffffffffu, s1, off);
        s2 += __shfl_xor_sync(0xffffffffu, s2, off);
    }
    if ((c & 31) == 0) {
        d_gnp_s[(b * 4 + g) * NN + n] = s1;
        d_gnp_q[(b * 4 + g) * NN + n] = s2;
    }
}

// ---------------- k5: GN stats (deterministic) ----------------
__global__ void gn_stats_kernel() {
    int bg = blockIdx.x;
    __shared__ double sh[256], sh2[256];
    double s = 0.0, q = 0.0;
    for (int i = threadIdx.x; i < NN; i += 256) {
        s += (double)d_gnp_s[bg * NN + i];
        q += (double)d_gnp_q[bg * NN + i];
    }
    sh[threadIdx.x] = s; sh2[threadIdx.x] = q;
    __syncthreads();
    for (int off = 128; off; off >>= 1) {
        if (threadIdx.x < off) { sh[threadIdx.x] += sh[threadIdx.x + off]; sh2[threadIdx.x] += sh2[threadIdx.x + off]; }
        __syncthreads();
    }
    if (threadIdx.x == 0) {
        double cnt = 32.0 * NN;
        double mean = sh[0] / cnt;
        double var = sh2[0] / cnt - mean * mean;
        d_gnm[bg] = (float)mean;
        d_gni[bg] = (float)(1.0 / sqrt(var + 1e-5));
    }
}

// ---------------- k6: fold GN into conv weights ----------------
__global__ void prepw_kernel(const float* __restrict__ conv_w, const float* __restrict__ conv_b,
                             const float* __restrict__ gn_g, const float* __restrict__ gn_b) {
    int b = blockIdx.x, o = threadIdx.x;
    float e = conv_b[o];
    for (int c = 0; c < 128; c++) {
        int g = c >> 5;
        float inv = d_gni[b * 4 + g];
        float A = gn_g[c] * inv;
        float D = gn_b[c] - d_gnm[b * 4 + g] * A;
        float w = conv_w[o * 128 + c];
        e = fmaf(w, D, e);
        d_WPT[(b * 128 + c) * 128 + o] = w * A;
    }
    d_E[b * 128 + o] = e;
}

// ---------------- k7: GEMM B  z[b][o][n] = sum_c WPT[b][c][o]*Y[b][n][c] + E ----------------
__global__ void __launch_bounds__(256) gemmB_kernel() {
    int b = blockIdx.y, n0 = blockIdx.x * 128;
    __shared__ __align__(16) float Ws[32 * 132];
    __shared__ __align__(16) float Ys[128 * 33];
    int tx = threadIdx.x & 15, ty = threadIdx.x >> 4;
    float acc[8][8];
    {
        float eb[8];
        #pragma unroll
        for (int i = 0; i < 8; i++) eb[i] = d_E[b * 128 + ty * 8 + i];
        #pragma unroll
        for (int j = 0; j < 8; j++)
            #pragma unroll
            for (int i = 0; i < 8; i++) acc[j][i] = eb[i];
    }
    for (int c0 = 0; c0 < 128; c0 += 32) {
        __syncthreads();
        for (int t = threadIdx.x; t < 32 * 128; t += 256) {
            int cc = t >> 7, oo = t & 127;
            Ws[cc * 132 + oo] = d_WPT[(b * 128 + c0 + cc) * 128 + oo];
            int nl = t >> 5, cl = t & 31;
            Ys[nl * 33 + cl] = d_Y[(b * NN + n0 + nl) * 128 + c0 + cl];
        }
        __syncthreads();
        #pragma unroll
        for (int cc = 0; cc < 32; cc++) {
            float4 w0 = *(const float4*)(Ws + cc * 132 + ty * 8);
            float4 w1 = *(const float4*)(Ws + cc * 132 + ty * 8 + 4);
            #pragma unroll
            for (int j = 0; j < 8; j++) {
                float yv = Ys[(tx + 16 * j) * 33 + cc];
                acc[j][0] = fmaf(w0.x, yv, acc[j][0]);
                acc[j][1] = fmaf(w0.y, yv, acc[j][1]);
                acc[j][2] = fmaf(w0.z, yv, acc[j][2]);
                acc[j][3] = fmaf(w0.w, yv, acc[j][3]);
                acc[j][4] = fmaf(w1.x, yv, acc[j][4]);
                acc[j][5] = fmaf(w1.y, yv, acc[j][5]);
                acc[j][6] = fmaf(w1.z, yv, acc[j][6]);
                acc[j][7] = fmaf(w1.w, yv, acc[j][7]);
            }
        }
    }
    #pragma unroll
    for (int j = 0; j < 8; j++) {
        int n = n0 + tx + 16 * j;
        #pragma unroll
        for (int i = 0; i < 8; i++)
            d_Z[(b * 128 + ty * 8 + i) * NN + n] = acc[j][i];
    }
    // deterministic per-block BN partials
    float* red = Ys;
    __syncthreads();
    #pragma unroll
    for (int i = 0; i < 8; i++) {
        float s = 0.f, q = 0.f;
        #pragma unroll
        for (int j = 0; j < 8; j++) { s += acc[j][i]; q = fmaf(acc[j][i], acc[j][i], q); }
        red[(ty * 8 + i) * 16 + tx] = s;
        red[2048 + (ty * 8 + i) * 16 + tx] = q;
    }
    __syncthreads();
    if (threadIdx.x < 128) {
        int o = threadIdx.x;
        float s = 0.f, q = 0.f;
        #pragma unroll
        for (int t = 0; t < 16; t++) { s += red[o * 16 + t]; q += red[2048 + o * 16 + t]; }
        int blk = blockIdx.y * 32 + blockIdx.x;
        d_bnp_s[o * 128 + blk] = s;
        d_bnp_q[o * 128 + blk] = q;
    }
}

// ---------------- k8: BN stats ----------------
__global__ void bn_stats_kernel() {
    int o = threadIdx.x;
    double s = 0.0, q = 0.0;
    for (int k = 0; k < 128; k++) { s += (double)d_bnp_s[o * 128 + k]; q += (double)d_bnp_q[o * 128 + k]; }
    double cnt = (double)(NB * NN);
    double mean = s / cnt;
    double var = q / cnt - mean * mean;
    d_bnm[o] = (float)mean;
    d_bni[o] = (float)(1.0 / sqrt(var + 1e-5));
}

// ---------------- k9: BN apply + relu ----------------
__global__ void final_kernel(const float* __restrict__ bn_g, const float* __restrict__ bn_b,
                             float* __restrict__ out) {
    int i = blockIdx.x * 256 + threadIdx.x;
    int o = (i >> 12) & 127;
    float v = (d_Z[i] - d_bnm[o]) * d_bni[o] * bn_g[o] + bn_b[o];
    out[i] = fmaxf(v, 0.f);
}

extern "C" void kernel_launch(void* const* d_in, const int* in_sizes, int n_in,
                              void* d_out, int out_size) {
    const float* x      = (const float*)d_in[0];
    const float* w_lin  = (const float*)d_in[1];
    const float* b_lin  = (const float*)d_in[2];
    const float* w_aw   = (const float*)d_in[3];
    const float* b_aw   = (const float*)d_in[4];
    const float* gn_g   = (const float*)d_in[5];
    const float* gn_b   = (const float*)d_in[6];
    const float* conv_w = (const float*)d_in[7];
    const float* conv_b = (const float*)d_in[8];
    const float* bn_g   = (const float*)d_in[9];
    const float* bn_b   = (const float*)d_in[10];
    float* out = (float*)d_out;

    cudaFuncSetAttribute(knn_kernel, cudaFuncAttributeMaxDynamicSharedMemorySize, KNN_SMEM_BYTES);

    prep_kernel<<<192, 256>>>(w_lin, b_lin, w_aw, b_aw);
    xx_kernel<<<64, 256>>>(x);
    dummy_kernel<<<1, 32>>>();   // keeps knn in the ncu-captured launch slot
    knn_kernel<<<dim3(128, 4), 128, KNN_SMEM_BYTES>>>(x);
    gemmA_kernel<<<dim3(32, 4, 3), 256>>>(x);
    attn_kernel<<<dim3(4096, 4), 128>>>(x);
    gn_stats_kernel<<<16, 256>>>();
    prepw_kernel<<<4, 128>>>(conv_w, conv_b, gn_g, gn_b);
    gemmB_kernel<<<dim3(32, 4), 256>>>();
    bn_stats_kernel<<<1, 128>>>();
    final_kernel<<<8192, 256>>>(bn_g, bn_b, out);
}

// round 12
// speedup vs baseline: 2.0780x; 1.3729x over previous
#include <cuda_runtime.h>
#include <cuda_bf16.h>
#include <stdint.h>
#include <math.h>

#define NB 4
#define NC 128
#define NN 4096
#define NK 9

// ---------------- device scratch ----------------
__device__ __align__(16) float d_WT[128 * 384];
__device__ float d_bias[384];
__device__ __align__(16) float d_xx[NB * NN];
__device__ int   d_knn_buf[NB * NN * NK];
__device__ __align__(16) float d_PQA[NB * NN * 384];
__device__ __align__(16) float d_Y[NB * NN * 128];
__device__ __align__(16) float d_Z[NB * 128 * NN];
__device__ float d_gnp_s[16 * NN];
__device__ float d_gnp_q[16 * NN];
__device__ float d_gnm[16], d_gni[16];
__device__ __align__(16) float d_WPT[NB * 128 * 128];
__device__ float d_E[NB * 128];
__device__ float d_bnp_s[128 * 128], d_bnp_q[128 * 128];
__device__ float d_bnm[128], d_bni[128];
// bf16 split of x, transposed to [b][n][c]
__device__ __align__(16) __nv_bfloat16 d_XH[NB * NN * 128];
__device__ __align__(16) __nv_bfloat16 d_XL[NB * NN * 128];

// ---------------- helpers ----------------
__device__ __forceinline__ uint32_t smem_u32(const void* p) {
    uint32_t a;
    asm("{ .reg .u64 t; cvta.to.shared.u64 t, %1; cvt.u32.u64 %0, t; }" : "=r"(a) : "l"(p));
    return a;
}
__device__ __forceinline__ void cpasync16(void* dst, const void* src) {
    unsigned s = (unsigned)__cvta_generic_to_shared(dst);
    asm volatile("cp.async.cg.shared.global [%0], [%1], 16;" :: "r"(s), "l"(src) : "memory");
}
#define CP_COMMIT() asm volatile("cp.async.commit_group;" ::: "memory")
#define CP_WAIT0()  asm volatile("cp.async.wait_group 0;" ::: "memory")

__device__ __forceinline__ void ldm_x4(uint32_t* r, uint32_t addr) {
    asm volatile("ldmatrix.sync.aligned.m8n8.x4.shared.b16 {%0,%1,%2,%3}, [%4];"
                 : "=r"(r[0]), "=r"(r[1]), "=r"(r[2]), "=r"(r[3]) : "r"(addr));
}
__device__ __forceinline__ void mma_bf16(float* d, const uint32_t* a, uint32_t b0, uint32_t b1) {
    asm volatile("mma.sync.aligned.m16n8k16.row.col.f32.bf16.bf16.f32 "
                 "{%0,%1,%2,%3}, {%4,%5,%6,%7}, {%8,%9}, {%0,%1,%2,%3};"
                 : "+f"(d[0]), "+f"(d[1]), "+f"(d[2]), "+f"(d[3])
                 : "r"(a[0]), "r"(a[1]), "r"(a[2]), "r"(a[3]), "r"(b0), "r"(b1));
}

// key: descending by value, ties -> smaller index first (matches lax.top_k)
__device__ __forceinline__ unsigned long long enckey(float v, int m) {
    unsigned u = __float_as_uint(v);
    unsigned mask = ((int)u < 0) ? 0xFFFFFFFFu : 0x80000000u;
    u ^= mask;
    return ((unsigned long long)u << 32) | (unsigned)(~m);
}

// ---------------- k0: combined weights (transposed) ----------------
__global__ void prep_kernel(const float* __restrict__ w_lin, const float* __restrict__ b_lin,
                            const float* __restrict__ w_aw, const float* __restrict__ b_aw) {
    int i = blockIdx.x * 256 + threadIdx.x;
    if (i >= 384 * 128) return;
    int o = i % 384, c = i / 384;
    float w = 0.f;
    if (o < 128)      w = w_lin[o * 256 + c] + w_lin[o * 256 + 128 + c];
    else if (o < 256) w = w_lin[(o - 128) * 256 + 128 + c];
    else if (o < 292) w = w_aw[(o - 256) * 128 + c];
    d_WT[c * 384 + o] = w;
    if (c == 0) {
        float bv = 0.f;
        if (o < 128) bv = b_lin[o];
        else if (o >= 256 && o < 292) bv = b_aw[o - 256];
        d_bias[o] = bv;
    }
}

// ---------------- k1: xx ----------------
__global__ void xx_kernel(const float* __restrict__ x) {
    int i = blockIdx.x * 256 + threadIdx.x;
    int b = i >> 12, n = i & (NN - 1);
    float s = 0.f;
    #pragma unroll 8
    for (int c = 0; c < 128; c++) {
        float v = x[(b * 128 + c) * NN + n];
        s = fmaf(v, v, s);
    }
    d_xx[i] = s;
}

// ---------------- k1b: transpose + bf16 split ----------------
__global__ void cvt_kernel(const float* __restrict__ x) {
    __shared__ float t[32][33];
    int b = blockIdx.z, ct = blockIdx.y, nt = blockIdx.x;
    int tx = threadIdx.x & 31, ty = threadIdx.x >> 5;
    #pragma unroll
    for (int it = 0; it < 4; it++) {
        int c = ct * 32 + ty + it * 8, n = nt * 32 + tx;
        t[ty + it * 8][tx] = x[(b * 128 + c) * NN + n];
    }
    __syncthreads();
    #pragma unroll
    for (int it = 0; it < 4; it++) {
        int nl = ty + it * 8, c = tx;
        float v = t[c][nl];
        __nv_bfloat16 h = __float2bfloat16(v);
        __nv_bfloat16 l = __float2bfloat16(v - __bfloat162float(h));
        int gi = (b * NN + nt * 32 + nl) * 128 + ct * 32 + c;
        d_XH[gi] = h;
        d_XL[gi] = l;
    }
}

// ---------------- k2: KNN via mma.sync bf16 (3-term split) ----------------
// Block = 128 query rows, 512 threads (16 warps: warpM=wid&7 -> 16 rows,
// warpN=wid>>3 -> 64 cols). Per m-tile: D = Ahi*Bhi + Ahi*Blo + Alo*Bhi.
// Tiles 128x128 bf16, rows of 256B, 16B chunks XOR-swizzled (c ^ (r&7)) so
// every ldmatrix 8-row read is bank-conflict-free.
#define SM_XX  0
#define SM_AHI 1024
#define SM_ALO (SM_AHI + 32768)
#define SM_B   (SM_ALO + 32768)
#define SM_BUF 65536
#define KNN_SMEM_BYTES (SM_B + 2 * SM_BUF)   // 197632

__device__ __forceinline__ void fill_rows(char* smem, int dstoff, const __nv_bfloat16* src, int tid) {
    #pragma unroll
    for (int i = 0; i < 4; i++) {
        int idx = i * 512 + tid;            // 2048 chunks = 128 rows x 256B
        int r = idx >> 4, c = idx & 15;
        cpasync16(smem + dstoff + r * 256 + ((c ^ (r & 7)) << 4), src + r * 128 + c * 8);
    }
}

__global__ void __launch_bounds__(512) knn_kernel() {
    extern __shared__ char smc[];
    const uint32_t sb = smem_u32(smc);
    const int b = blockIdx.y, n0 = blockIdx.x * 128;
    const int tid = threadIdx.x, wid = tid >> 5, lane = tid & 31;
    const int warpM = wid & 7, warpN = wid >> 3;

    // prolog: A (queries, hi+lo), B tile 0 (hi+lo), xx tile 0
    fill_rows(smc, SM_AHI, d_XH + (b * NN + n0) * 128, tid);
    fill_rows(smc, SM_ALO, d_XL + (b * NN + n0) * 128, tid);
    fill_rows(smc, SM_B,           d_XH + (b * NN) * 128, tid);
    fill_rows(smc, SM_B + 32768,   d_XL + (b * NN) * 128, tid);
    if (tid < 32) cpasync16(smc + SM_XX + tid * 16, d_xx + b * NN + tid * 4);
    CP_COMMIT();

    // ldmatrix address components
    const int arow = warpM * 16 + (lane & 15);
    const uint32_t aoff = (uint32_t)(arow * 256);
    const int asw = arow & 7;
    const int bmtx = lane >> 3;
    const int brow_base = warpN * 64 + (lane & 7) + (bmtx & 1) * 8;
    const int bchunk_add = bmtx >> 1;

    unsigned long long L0[9], L1[9];
    #pragma unroll
    for (int q = 0; q < 9; q++) { L0[q] = 0ull; L1[q] = 0ull; }
    unsigned long long th0 = 0ull, th1 = 0ull;

    for (int mt = 0; mt < 32; mt++) {
        const int m0 = mt * 128, s = mt & 1;
        CP_WAIT0();
        __syncthreads();

        if (mt < 31) {
            int sn = (mt + 1) & 1, m0n = m0 + 128;
            fill_rows(smc, SM_B + sn * SM_BUF,         d_XH + (b * NN + m0n) * 128, tid);
            fill_rows(smc, SM_B + sn * SM_BUF + 32768, d_XL + (b * NN + m0n) * 128, tid);
            if (tid < 32) cpasync16(smc + SM_XX + sn * 512 + tid * 16, d_xx + b * NN + m0n + tid * 4);
            CP_COMMIT();
        }

        float acc[8][4];
        #pragma unroll
        for (int p = 0; p < 8; p++)
            #pragma unroll
            for (int i = 0; i < 4; i++) acc[p][i] = 0.f;

        const uint32_t bh = sb + SM_B + s * SM_BUF;
        const uint32_t bl = bh + 32768;
        #pragma unroll
        for (int part = 0; part < 3; part++) {
            const uint32_t aBase = (part == 2) ? (sb + SM_ALO) : (sb + SM_AHI);
            const uint32_t bBase = (part == 1) ? bl : bh;
            #pragma unroll
            for (int ks = 0; ks < 8; ks++) {
                uint32_t af[4];
                {
                    int chunk = ks * 2 + (lane >> 4);
                    ldm_x4(af, aBase + aoff + ((chunk ^ asw) << 4));
                }
                #pragma unroll
                for (int p = 0; p < 4; p++) {
                    uint32_t bf[4];
                    int nrow = brow_base + p * 16;
                    int chunk = ks * 2 + bchunk_add;
                    ldm_x4(bf, bBase + nrow * 256 + ((chunk ^ (nrow & 7)) << 4));
                    mma_bf16(acc[p * 2],     af, bf[0], bf[2]);
                    mma_bf16(acc[p * 2 + 1], af, bf[1], bf[3]);
                }
            }
        }

        // selection: rows r0 = warpM*16 + lane/4, r1 = r0+8;
        // cols nl = warpN*64 + s8*8 + (lane&3)*2 + {0,1}
        const float* xxS = (const float*)(smc + SM_XX + s * 512);
        const int colb = warpN * 64 + (lane & 3) * 2;
        #pragma unroll
        for (int s8 = 0; s8 < 8; s8++) {
            int nl = colb + s8 * 8;
            float xa = xxS[nl], xb2 = xxS[nl + 1];
            int ma = m0 + nl, mb2 = ma + 1;
            unsigned long long k;
            k = enckey(2.f * acc[s8][0] - xa, ma);
            if (k > th0) {
                #pragma unroll
                for (int q = 0; q < 9; q++) { unsigned long long c = L0[q]; if (k > c) { L0[q] = k; k = c; } }
                th0 = L0[8];
            }
            k = enckey(2.f * acc[s8][1] - xb2, mb2);
            if (k > th0) {
                #pragma unroll
                for (int q = 0; q < 9; q++) { unsigned long long c = L0[q]; if (k > c) { L0[q] = k; k = c; } }
                th0 = L0[8];
            }
            k = enckey(2.f * acc[s8][2] - xa, ma);
            if (k > th1) {
                #pragma unroll
                for (int q = 0; q < 9; q++) { unsigned long long c = L1[q]; if (k > c) { L1[q] = k; k = c; } }
                th1 = L1[8];
            }
            k = enckey(2.f * acc[s8][3] - xb2, mb2);
            if (k > th1) {
                #pragma unroll
                for (int q = 0; q < 9; q++) { unsigned long long c = L1[q]; if (k > c) { L1[q] = k; k = c; } }
                th1 = L1[8];
            }
        }
    }

    // merge: 8 lists per row (2 warpN x 4 lane&3), reuse B area as scratch
    __syncthreads();
    unsigned long long* M = (unsigned long long*)(smc + SM_B);
    {
        int r0 = warpM * 16 + (lane >> 2), src = warpN * 4 + (lane & 3);
        #pragma unroll
        for (int q = 0; q < 9; q++) {
            M[(r0 * 8 + src) * 9 + q]       = L0[q];
            M[((r0 + 8) * 8 + src) * 9 + q] = L1[q];
        }
    }
    __syncthreads();
    if (tid < 128) {
        const unsigned long long* base = M + tid * 72;
        int h[8];
        #pragma unroll
        for (int l = 0; l < 8; l++) h[l] = 0;
        for (int q = 0; q < 9; q++) {
            unsigned long long best = 0; int bl2 = 0;
            #pragma unroll
            for (int l = 0; l < 8; l++) {
                if (h[l] < 9) {
                    unsigned long long kk = base[l * 9 + h[l]];
                    if (kk > best) { best = kk; bl2 = l; }
                }
            }
            h[bl2]++;
            d_knn_buf[(b * NN + n0 + tid) * NK + q] = (int)(~(unsigned)(best & 0xFFFFFFFFu));
        }
    }
}

// ---------------- k3: GEMM A ----------------
__global__ void __launch_bounds__(256) gemmA_kernel(const float* __restrict__ x) {
    int b = blockIdx.y, n0 = blockIdx.x * 128, o0 = blockIdx.z * 128;
    __shared__ __align__(16) float Ws[32 * 132];
    __shared__ __align__(16) float Xs[32 * 132];
    int tx = threadIdx.x & 15, ty = threadIdx.x >> 4;
    float acc[8][8];
    {
        float bias[8];
        #pragma unroll
        for (int i = 0; i < 8; i++) bias[i] = d_bias[o0 + ty * 8 + i];
        #pragma unroll
        for (int j = 0; j < 8; j++)
            #pragma unroll
            for (int i = 0; i < 8; i++) acc[j][i] = bias[i];
    }
    for (int c0 = 0; c0 < 128; c0 += 32) {
        __syncthreads();
        for (int t = threadIdx.x; t < 32 * 128; t += 256) {
            int cc = t >> 7, oo = t & 127;
            Ws[cc * 132 + oo] = d_WT[(c0 + cc) * 384 + o0 + oo];
            Xs[cc * 132 + oo] = x[(b * 128 + c0 + cc) * NN + n0 + oo];
        }
        __syncthreads();
        #pragma unroll
        for (int cc = 0; cc < 32; cc++) {
            float4 w0 = *(const float4*)(Ws + cc * 132 + ty * 8);
            float4 w1 = *(const float4*)(Ws + cc * 132 + ty * 8 + 4);
            #pragma unroll
            for (int j = 0; j < 8; j++) {
                float xv = Xs[cc * 132 + tx + 16 * j];
                acc[j][0] = fmaf(w0.x, xv, acc[j][0]);
                acc[j][1] = fmaf(w0.y, xv, acc[j][1]);
                acc[j][2] = fmaf(w0.z, xv, acc[j][2]);
                acc[j][3] = fmaf(w0.w, xv, acc[j][3]);
                acc[j][4] = fmaf(w1.x, xv, acc[j][4]);
                acc[j][5] = fmaf(w1.y, xv, acc[j][5]);
                acc[j][6] = fmaf(w1.z, xv, acc[j][6]);
                acc[j][7] = fmaf(w1.w, xv, acc[j][7]);
            }
        }
    }
    #pragma unroll
    for (int j = 0; j < 8; j++) {
        int n = n0 + tx + 16 * j;
        float* dp = d_PQA + (b * NN + n) * 384 + o0 + ty * 8;
        *(float4*)dp       = make_float4(acc[j][0], acc[j][1], acc[j][2], acc[j][3]);
        *(float4*)(dp + 4) = make_float4(acc[j][4], acc[j][5], acc[j][6], acc[j][7]);
    }
}

// ---------------- k4: per-point attention ----------------
__global__ void __launch_bounds__(128) attn_kernel(const float* __restrict__ x) {
    int n = blockIdx.x, b = blockIdx.y;
    int c = threadIdx.x, g = c >> 5;
    __shared__ float fS[9 * 132];
    __shared__ float sS[4 * 81];
    __shared__ float awS[36], tS[36];
    __shared__ int idxS[9];
    int base = (b * NN + n) * 384;
    if (c < 9)  idxS[c] = d_knn_buf[(b * NN + n) * NK + c];
    if (c < 36) awS[c] = d_PQA[base + 256 + c];
    __syncthreads();
    float P = d_PQA[base + c];
    float e9[9];
    #pragma unroll
    for (int k = 0; k < 9; k++) {
        float f = P - d_PQA[(b * NN + idxS[k]) * 384 + 128 + c];
        fS[k * 132 + c] = f;
        e9[k] = f > 0.f ? f : expm1f(f);
    }
    if (c < 4) {
        float* row = awS + c * 9;
        float mx = row[0];
        #pragma unroll
        for (int k = 1; k < 9; k++) mx = fmaxf(mx, row[k]);
        float sm = 0.f;
        #pragma unroll
        for (int k = 0; k < 9; k++) { float e = expf(row[k] - mx); row[k] = e; sm += e; }
        float inv = 1.f / sm;
        #pragma unroll
        for (int k = 0; k < 9; k++) row[k] *= inv;
    }
    __syncthreads();
    for (int t = c; t < 324; t += 128) {
        int g2 = t / 81, p = t % 81, k = p / 9, j = p % 9;
        const float* fa = fS + k * 132 + g2 * 32;
        const float* fb = fS + j * 132 + g2 * 32;
        float s = 0.f;
        #pragma unroll
        for (int q = 0; q < 32; q++) s = fmaf(fa[q], fb[q], s);
        sS[g2 * 81 + p] = s * 0.17677669529663689f;
    }
    __syncthreads();
    if (c < 36) {
        float* row = sS + (c / 9) * 81 + (c % 9) * 9;
        float mx = row[0];
        #pragma unroll
        for (int j = 1; j < 9; j++) mx = fmaxf(mx, row[j]);
        float sm = 0.f;
        #pragma unroll
        for (int j = 0; j < 9; j++) { float e = expf(row[j] - mx); row[j] = e; sm += e; }
        float inv = 1.f / sm;
        #pragma unroll
        for (int j = 0; j < 9; j++) row[j] *= inv;
    }
    __syncthreads();
    if (c < 36) {
        int g2 = c / 9, j = c % 9;
        float tv = 0.f;
        #pragma unroll
        for (int k = 0; k < 9; k++) tv = fmaf(awS[g2 * 9 + k], sS[g2 * 81 + k * 9 + j], tv);
        tS[c] = tv;
    }
    __syncthreads();
    float lf = 0.f;
    #pragma unroll
    for (int j = 0; j < 9; j++) lf = fmaf(tS[g * 9 + j], e9[j], lf);
    float yv = lf + x[(b * 128 + c) * NN + n];
    d_Y[(b * NN + n) * 128 + c] = yv;
    float s1 = yv, s2 = yv * yv;
    #pragma unroll
    for (int off = 16; off; off >>= 1) {
        s1 += __shfl_xor_sync(0xffffffffu, s1, off);
        s2 += __shfl_xor_sync(0xffffffffu, s2, off);
    }
    if ((c & 31) == 0) {
        d_gnp_s[(b * 4 + g) * NN + n] = s1;
        d_gnp_q[(b * 4 + g) * NN + n] = s2;
    }
}

// ---------------- k5: GN stats ----------------
__global__ void gn_stats_kernel() {
    int bg = blockIdx.x;
    __shared__ double sh[256], sh2[256];
    double s = 0.0, q = 0.0;
    for (int i = threadIdx.x; i < NN; i += 256) {
        s += (double)d_gnp_s[bg * NN + i];
        q += (double)d_gnp_q[bg * NN + i];
    }
    sh[threadIdx.x] = s; sh2[threadIdx.x] = q;
    __syncthreads();
    for (int off = 128; off; off >>= 1) {
        if (threadIdx.x < off) { sh[threadIdx.x] += sh[threadIdx.x + off]; sh2[threadIdx.x] += sh2[threadIdx.x + off]; }
        __syncthreads();
    }
    if (threadIdx.x == 0) {
        double cnt = 32.0 * NN;
        double mean = sh[0] / cnt;
        double var = sh2[0] / cnt - mean * mean;
        d_gnm[bg] = (float)mean;
        d_gni[bg] = (float)(1.0 / sqrt(var + 1e-5));
    }
}

// ---------------- k6: fold GN into conv weights ----------------
__global__ void prepw_kernel(const float* __restrict__ conv_w, const float* __restrict__ conv_b,
                             const float* __restrict__ gn_g, const float* __restrict__ gn_b) {
    int b = blockIdx.x, o = threadIdx.x;
    float e = conv_b[o];
    for (int c = 0; c < 128; c++) {
        int g = c >> 5;
        float inv = d_gni[b * 4 + g];
        float A = gn_g[c] * inv;
        float D = gn_b[c] - d_gnm[b * 4 + g] * A;
        float w = conv_w[o * 128 + c];
        e = fmaf(w, D, e);
        d_WPT[(b * 128 + c) * 128 + o] = w * A;
    }
    d_E[b * 128 + o] = e;
}

// ---------------- k7: GEMM B ----------------
__global__ void __launch_bounds__(256) gemmB_kernel() {
    int b = blockIdx.y, n0 = blockIdx.x * 128;
    __shared__ __align__(16) float Ws[32 * 132];
    __shared__ __align__(16) float Ys[128 * 33];
    int tx = threadIdx.x & 15, ty = threadIdx.x >> 4;
    float acc[8][8];
    {
        float eb[8];
        #pragma unroll
        for (int i = 0; i < 8; i++) eb[i] = d_E[b * 128 + ty * 8 + i];
        #pragma unroll
        for (int j = 0; j < 8; j++)
            #pragma unroll
            for (int i = 0; i < 8; i++) acc[j][i] = eb[i];
    }
    for (int c0 = 0; c0 < 128; c0 += 32) {
        __syncthreads();
        for (int t = threadIdx.x; t < 32 * 128; t += 256) {
            int cc = t >> 7, oo = t & 127;
            Ws[cc * 132 + oo] = d_WPT[(b * 128 + c0 + cc) * 128 + oo];
            int nl = t >> 5, cl = t & 31;
            Ys[nl * 33 + cl] = d_Y[(b * NN + n0 + nl) * 128 + c0 + cl];
        }
        __syncthreads();
        #pragma unroll
        for (int cc = 0; cc < 32; cc++) {
            float4 w0 = *(const float4*)(Ws + cc * 132 + ty * 8);
            float4 w1 = *(const float4*)(Ws + cc * 132 + ty * 8 + 4);
            #pragma unroll
            for (int j = 0; j < 8; j++) {
                float yv = Ys[(tx + 16 * j) * 33 + cc];
                acc[j][0] = fmaf(w0.x, yv, acc[j][0]);
                acc[j][1] = fmaf(w0.y, yv, acc[j][1]);
                acc[j][2] = fmaf(w0.z, yv, acc[j][2]);
                acc[j][3] = fmaf(w0.w, yv, acc[j][3]);
                acc[j][4] = fmaf(w1.x, yv, acc[j][4]);
                acc[j][5] = fmaf(w1.y, yv, acc[j][5]);
                acc[j][6] = fmaf(w1.z, yv, acc[j][6]);
                acc[j][7] = fmaf(w1.w, yv, acc[j][7]);
            }
        }
    }
    #pragma unroll
    for (int j = 0; j < 8; j++) {
        int n = n0 + tx + 16 * j;
        #pragma unroll
        for (int i = 0; i < 8; i++)
            d_Z[(b * 128 + ty * 8 + i) * NN + n] = acc[j][i];
    }
    float* red = Ys;
    __syncthreads();
    #pragma unroll
    for (int i = 0; i < 8; i++) {
        float s = 0.f, q = 0.f;
        #pragma unroll
        for (int j = 0; j < 8; j++) { s += acc[j][i]; q = fmaf(acc[j][i], acc[j][i], q); }
        red[(ty * 8 + i) * 16 + tx] = s;
        red[2048 + (ty * 8 + i) * 16 + tx] = q;
    }
    __syncthreads();
    if (threadIdx.x < 128) {
        int o = threadIdx.x;
        float s = 0.f, q = 0.f;
        #pragma unroll
        for (int t = 0; t < 16; t++) { s += red[o * 16 + t]; q += red[2048 + o * 16 + t]; }
        int blk = blockIdx.y * 32 + blockIdx.x;
        d_bnp_s[o * 128 + blk] = s;
        d_bnp_q[o * 128 + blk] = q;
    }
}

// ---------------- k8: BN stats ----------------
__global__ void bn_stats_kernel() {
    int o = threadIdx.x;
    double s = 0.0, q = 0.0;
    for (int k = 0; k < 128; k++) { s += (double)d_bnp_s[o * 128 + k]; q += (double)d_bnp_q[o * 128 + k]; }
    double cnt = (double)(NB * NN);
    double mean = s / cnt;
    double var = q / cnt - mean * mean;
    d_bnm[o] = (float)mean;
    d_bni[o] = (float)(1.0 / sqrt(var + 1e-5));
}

// ---------------- k9: BN apply + relu ----------------
__global__ void final_kernel(const float* __restrict__ bn_g, const float* __restrict__ bn_b,
                             float* __restrict__ out) {
    int i = blockIdx.x * 256 + threadIdx.x;
    int o = (i >> 12) & 127;
    float v = (d_Z[i] - d_bnm[o]) * d_bni[o] * bn_g[o] + bn_b[o];
    out[i] = fmaxf(v, 0.f);
}

extern "C" void kernel_launch(void* const* d_in, const int* in_sizes, int n_in,
                              void* d_out, int out_size) {
    const float* x      = (const float*)d_in[0];
    const float* w_lin  = (const float*)d_in[1];
    const float* b_lin  = (const float*)d_in[2];
    const float* w_aw   = (const float*)d_in[3];
    const float* b_aw   = (const float*)d_in[4];
    const float* gn_g   = (const float*)d_in[5];
    const float* gn_b   = (const float*)d_in[6];
    const float* conv_w = (const float*)d_in[7];
    const float* conv_b = (const float*)d_in[8];
    const float* bn_g   = (const float*)d_in[9];
    const float* bn_b   = (const float*)d_in[10];
    float* out = (float*)d_out;

    cudaFuncSetAttribute(knn_kernel, cudaFuncAttributeMaxDynamicSharedMemorySize, KNN_SMEM_BYTES);

    prep_kernel<<<192, 256>>>(w_lin, b_lin, w_aw, b_aw);
    xx_kernel<<<64, 256>>>(x);
    cvt_kernel<<<dim3(128, 4, 4), 256>>>(x);
    knn_kernel<<<dim3(32, 4), 512, KNN_SMEM_BYTES>>>();
    gemmA_kernel<<<dim3(32, 4, 3), 256>>>(x);
    attn_kernel<<<dim3(4096, 4), 128>>>(x);
    gn_stats_kernel<<<16, 256>>>();
    prepw_kernel<<<4, 128>>>(conv_w, conv_b, gn_g, gn_b);
    gemmB_kernel<<<dim3(32, 4), 256>>>();
    bn_stats_kernel<<<1, 128>>>();
    final_kernel<<<8192, 256>>>(bn_g, bn_b, out);
}

// round 13
// speedup vs baseline: 2.7581x; 1.3273x over previous
#include <cuda_runtime.h>
#include <cuda_bf16.h>
#include <stdint.h>
#include <math.h>

#define NB 4
#define NC 128
#define NN 4096
#define NK 9

// ---------------- device scratch ----------------
__device__ __align__(16) float d_WT[128 * 384];
__device__ float d_bias[384];
__device__ __align__(16) float d_xx[NB * NN];
__device__ int   d_knn_buf[NB * NN * NK];
__device__ __align__(16) float d_PQA[NB * NN * 384];
__device__ __align__(16) float d_Y[NB * NN * 128];
__device__ __align__(16) float d_Z[NB * 128 * NN];
__device__ float d_gnp_s[16 * NN];
__device__ float d_gnp_q[16 * NN];
__device__ float d_gnm[16], d_gni[16];
__device__ __align__(16) float d_WPT[NB * 128 * 128];
__device__ float d_E[NB * 128];
__device__ float d_bnp_s[128 * 128], d_bnp_q[128 * 128];
__device__ float d_bnm[128], d_bni[128];
// bf16 split of x, transposed to [b][n][c]
__device__ __align__(16) __nv_bfloat16 d_XH[NB * NN * 128];
__device__ __align__(16) __nv_bfloat16 d_XL[NB * NN * 128];

// ---------------- helpers ----------------
__device__ __forceinline__ uint32_t smem_u32(const void* p) {
    uint32_t a;
    asm("{ .reg .u64 t; cvta.to.shared.u64 t, %1; cvt.u32.u64 %0, t; }" : "=r"(a) : "l"(p));
    return a;
}
__device__ __forceinline__ void cpasync16(void* dst, const void* src) {
    unsigned s = (unsigned)__cvta_generic_to_shared(dst);
    asm volatile("cp.async.cg.shared.global [%0], [%1], 16;" :: "r"(s), "l"(src) : "memory");
}
#define CP_COMMIT() asm volatile("cp.async.commit_group;" ::: "memory")
#define CP_WAIT0()  asm volatile("cp.async.wait_group 0;" ::: "memory")

__device__ __forceinline__ void ldm_x4(uint32_t* r, uint32_t addr) {
    asm volatile("ldmatrix.sync.aligned.m8n8.x4.shared.b16 {%0,%1,%2,%3}, [%4];"
                 : "=r"(r[0]), "=r"(r[1]), "=r"(r[2]), "=r"(r[3]) : "r"(addr));
}
__device__ __forceinline__ void mma_bf16(float* d, const uint32_t* a, uint32_t b0, uint32_t b1) {
    asm volatile("mma.sync.aligned.m16n8k16.row.col.f32.bf16.bf16.f32 "
                 "{%0,%1,%2,%3}, {%4,%5,%6,%7}, {%8,%9}, {%0,%1,%2,%3};"
                 : "+f"(d[0]), "+f"(d[1]), "+f"(d[2]), "+f"(d[3])
                 : "r"(a[0]), "r"(a[1]), "r"(a[2]), "r"(a[3]), "r"(b0), "r"(b1));
}

// key: descending by value, ties -> smaller index first (matches lax.top_k)
__device__ __forceinline__ unsigned long long enckey(float v, int m) {
    unsigned u = __float_as_uint(v);
    unsigned mask = ((int)u < 0) ? 0xFFFFFFFFu : 0x80000000u;
    u ^= mask;
    return ((unsigned long long)u << 32) | (unsigned)(~m);
}
// decode the value half of a key back to float (for the fast-path threshold)
__device__ __forceinline__ float dec_th(unsigned long long key) {
    uint32_t hi = (uint32_t)(key >> 32);
    return (hi & 0x80000000u) ? __uint_as_float(hi ^ 0x80000000u) : __uint_as_float(~hi);
}
// enckey(-inf, 0x7fffffff): value 0x007FFFFF, index ~0x7fffffff
#define NEG_KEY 0x007FFFFF80000000ull

// ---------------- k0: combined weights (transposed) ----------------
__global__ void prep_kernel(const float* __restrict__ w_lin, const float* __restrict__ b_lin,
                            const float* __restrict__ w_aw, const float* __restrict__ b_aw) {
    int i = blockIdx.x * 256 + threadIdx.x;
    if (i >= 384 * 128) return;
    int o = i % 384, c = i / 384;
    float w = 0.f;
    if (o < 128)      w = w_lin[o * 256 + c] + w_lin[o * 256 + 128 + c];
    else if (o < 256) w = w_lin[(o - 128) * 256 + 128 + c];
    else if (o < 292) w = w_aw[(o - 256) * 128 + c];
    d_WT[c * 384 + o] = w;
    if (c == 0) {
        float bv = 0.f;
        if (o < 128) bv = b_lin[o];
        else if (o >= 256 && o < 292) bv = b_aw[o - 256];
        d_bias[o] = bv;
    }
}

// ---------------- k1: xx ----------------
__global__ void xx_kernel(const float* __restrict__ x) {
    int i = blockIdx.x * 256 + threadIdx.x;
    int b = i >> 12, n = i & (NN - 1);
    float s = 0.f;
    #pragma unroll 8
    for (int c = 0; c < 128; c++) {
        float v = x[(b * 128 + c) * NN + n];
        s = fmaf(v, v, s);
    }
    d_xx[i] = s;
}

// ---------------- k1b: transpose + bf16 split ----------------
__global__ void cvt_kernel(const float* __restrict__ x) {
    __shared__ float t[32][33];
    int b = blockIdx.z, ct = blockIdx.y, nt = blockIdx.x;
    int tx = threadIdx.x & 31, ty = threadIdx.x >> 5;
    #pragma unroll
    for (int it = 0; it < 4; it++) {
        int c = ct * 32 + ty + it * 8, n = nt * 32 + tx;
        t[ty + it * 8][tx] = x[(b * 128 + c) * NN + n];
    }
    __syncthreads();
    #pragma unroll
    for (int it = 0; it < 4; it++) {
        int nl = ty + it * 8, c = tx;
        float v = t[c][nl];
        __nv_bfloat16 h = __float2bfloat16(v);
        __nv_bfloat16 l = __float2bfloat16(v - __bfloat162float(h));
        int gi = (b * NN + nt * 32 + nl) * 128 + ct * 32 + c;
        d_XH[gi] = h;
        d_XL[gi] = l;
    }
}

// ---------------- k2: KNN via mma.sync bf16 (3-term split) ----------------
// Block = 128 query rows, 512 threads (16 warps: warpM=wid&7 -> 16 rows,
// warpN=wid>>3 -> 64 cols, processed as two 32-col halves to keep regs < 128
// -- R11 hit the 128-reg cap and spilled ~5x instruction inflation).
// Phase 1 reuses the Bhi fragments for both Ahi and Alo terms; phase 2 is
// Ahi*Blo. Selection uses a float-threshold fast path (enckey only on pass).
#define SM_XX  0
#define SM_AHI 1024
#define SM_ALO (SM_AHI + 32768)
#define SM_B   (SM_ALO + 32768)
#define SM_BUF 65536
#define KNN_SMEM_BYTES (SM_B + 2 * SM_BUF)   // 197632

__device__ __forceinline__ void fill_rows(char* smem, int dstoff, const __nv_bfloat16* src, int tid) {
    #pragma unroll
    for (int i = 0; i < 4; i++) {
        int idx = i * 512 + tid;            // 2048 chunks = 128 rows x 256B
        int r = idx >> 4, c = idx & 15;
        cpasync16(smem + dstoff + r * 256 + ((c ^ (r & 7)) << 4), src + r * 128 + c * 8);
    }
}

#define INSERT9(Lst, thf, keyv) do { \
    unsigned long long _k = (keyv); \
    _Pragma("unroll") \
    for (int _q = 0; _q < 9; _q++) { \
        unsigned long long _c = (Lst)[_q]; \
        if (_k > _c) { (Lst)[_q] = _k; _k = _c; } \
    } \
    (thf) = dec_th((Lst)[8]); \
} while (0)

__global__ void __launch_bounds__(512) knn_kernel() {
    extern __shared__ char smc[];
    const uint32_t sb = smem_u32(smc);
    const int b = blockIdx.y, n0 = blockIdx.x * 128;
    const int tid = threadIdx.x, wid = tid >> 5, lane = tid & 31;
    const int warpM = wid & 7, warpN = wid >> 3;

    // prolog: A (queries, hi+lo), B tile 0 (hi+lo), xx tile 0
    fill_rows(smc, SM_AHI, d_XH + (b * NN + n0) * 128, tid);
    fill_rows(smc, SM_ALO, d_XL + (b * NN + n0) * 128, tid);
    fill_rows(smc, SM_B,           d_XH + (b * NN) * 128, tid);
    fill_rows(smc, SM_B + 32768,   d_XL + (b * NN) * 128, tid);
    if (tid < 32) cpasync16(smc + SM_XX + tid * 16, d_xx + b * NN + tid * 4);
    CP_COMMIT();

    // ldmatrix address components
    const int arow = warpM * 16 + (lane & 15);
    const int asw = arow & 7;
    const int ahalf = lane >> 4;
    const uint32_t aH = sb + SM_AHI + (uint32_t)(arow * 256);
    const uint32_t aL = sb + SM_ALO + (uint32_t)(arow * 256);
    const int bmtx = lane >> 3;
    const int brow_loc = (lane & 7) + (bmtx & 1) * 8;   // local row within a 16-row group
    const int bchunk_add = bmtx >> 1;
    const int bsw = brow_loc & 7;

    unsigned long long L0[9], L1[9];
    #pragma unroll
    for (int q = 0; q < 9; q++) { L0[q] = NEG_KEY; L1[q] = NEG_KEY; }
    float thf0 = -INFINITY, thf1 = -INFINITY;

    for (int mt = 0; mt < 32; mt++) {
        const int m0 = mt * 128, s = mt & 1;
        CP_WAIT0();
        __syncthreads();

        if (mt < 31) {
            int sn = (mt + 1) & 1, m0n = m0 + 128;
            fill_rows(smc, SM_B + sn * SM_BUF,         d_XH + (b * NN + m0n) * 128, tid);
            fill_rows(smc, SM_B + sn * SM_BUF + 32768, d_XL + (b * NN + m0n) * 128, tid);
            if (tid < 32) cpasync16(smc + SM_XX + sn * 512 + tid * 16, d_xx + b * NN + m0n + tid * 4);
            CP_COMMIT();
        }

        const uint32_t bh = sb + SM_B + s * SM_BUF;
        const uint32_t bl = bh + 32768;
        const float* xxS = (const float*)(smc + SM_XX + s * 512);

        #pragma unroll
        for (int half = 0; half < 2; half++) {
            float acc[4][4];
            #pragma unroll
            for (int g = 0; g < 4; g++)
                #pragma unroll
                for (int i = 0; i < 4; i++) acc[g][i] = 0.f;

            const int rbase = warpN * 64 + half * 32 + brow_loc;
            const uint32_t nb0 = (uint32_t)(rbase * 256);
            const uint32_t nb1 = (uint32_t)((rbase + 16) * 256);

            // phase 1: Bhi x (Ahi, Alo) -- one B load feeds both A terms
            #pragma unroll
            for (int ks = 0; ks < 8; ks++) {
                uint32_t afh[4], afl[4], bf0[4], bf1[4];
                uint32_t ac  = (uint32_t)(((ks * 2 + ahalf) ^ asw) << 4);
                uint32_t bco = (uint32_t)(((ks * 2 + bchunk_add) ^ bsw) << 4);
                ldm_x4(afh, aH + ac);
                ldm_x4(afl, aL + ac);
                ldm_x4(bf0, bh + nb0 + bco);
                ldm_x4(bf1, bh + nb1 + bco);
                mma_bf16(acc[0], afh, bf0[0], bf0[2]);
                mma_bf16(acc[1], afh, bf0[1], bf0[3]);
                mma_bf16(acc[2], afh, bf1[0], bf1[2]);
                mma_bf16(acc[3], afh, bf1[1], bf1[3]);
                mma_bf16(acc[0], afl, bf0[0], bf0[2]);
                mma_bf16(acc[1], afl, bf0[1], bf0[3]);
                mma_bf16(acc[2], afl, bf1[0], bf1[2]);
                mma_bf16(acc[3], afl, bf1[1], bf1[3]);
            }
            // phase 2: Blo x Ahi
            #pragma unroll
            for (int ks = 0; ks < 8; ks++) {
                uint32_t afh[4], bf0[4], bf1[4];
                uint32_t ac  = (uint32_t)(((ks * 2 + ahalf) ^ asw) << 4);
                uint32_t bco = (uint32_t)(((ks * 2 + bchunk_add) ^ bsw) << 4);
                ldm_x4(afh, aH + ac);
                ldm_x4(bf0, bl + nb0 + bco);
                ldm_x4(bf1, bl + nb1 + bco);
                mma_bf16(acc[0], afh, bf0[0], bf0[2]);
                mma_bf16(acc[1], afh, bf0[1], bf0[3]);
                mma_bf16(acc[2], afh, bf1[0], bf1[2]);
                mma_bf16(acc[3], afh, bf1[1], bf1[3]);
            }

            // selection: col groups g -> cols warpN*64 + half*32 + g*8 + (lane&3)*2 + {0,1}
            const int colb = warpN * 64 + half * 32 + (lane & 3) * 2;
            #pragma unroll
            for (int g = 0; g < 4; g++) {
                int nl = colb + g * 8;
                float xa = xxS[nl], xb2 = xxS[nl + 1];
                int ma = m0 + nl;
                float v;
                v = fmaf(2.f, acc[g][0], -xa);
                if (v >= thf0) INSERT9(L0, thf0, enckey(v, ma));
                v = fmaf(2.f, acc[g][1], -xb2);
                if (v >= thf0) INSERT9(L0, thf0, enckey(v, ma + 1));
                v = fmaf(2.f, acc[g][2], -xa);
                if (v >= thf1) INSERT9(L1, thf1, enckey(v, ma));
                v = fmaf(2.f, acc[g][3], -xb2);
                if (v >= thf1) INSERT9(L1, thf1, enckey(v, ma + 1));
            }
        }
    }

    // merge: 8 lists per row (2 warpN x 4 lane&3), reuse B area as scratch
    __syncthreads();
    unsigned long long* M = (unsigned long long*)(smc + SM_B);
    {
        int r0 = warpM * 16 + (lane >> 2), src = warpN * 4 + (lane & 3);
        #pragma unroll
        for (int q = 0; q < 9; q++) {
            M[(r0 * 8 + src) * 9 + q]       = L0[q];
            M[((r0 + 8) * 8 + src) * 9 + q] = L1[q];
        }
    }
    __syncthreads();
    if (tid < 128) {
        const unsigned long long* base = M + tid * 72;
        int h[8];
        #pragma unroll
        for (int l = 0; l < 8; l++) h[l] = 0;
        for (int q = 0; q < 9; q++) {
            unsigned long long best = 0; int bl2 = 0;
            #pragma unroll
            for (int l = 0; l < 8; l++) {
                if (h[l] < 9) {
                    unsigned long long kk = base[l * 9 + h[l]];
                    if (kk > best) { best = kk; bl2 = l; }
                }
            }
            h[bl2]++;
            d_knn_buf[(b * NN + n0 + tid) * NK + q] = (int)(~(unsigned)(best & 0xFFFFFFFFu));
        }
    }
}

// ---------------- k3: GEMM A ----------------
__global__ void __launch_bounds__(256) gemmA_kernel(const float* __restrict__ x) {
    int b = blockIdx.y, n0 = blockIdx.x * 128, o0 = blockIdx.z * 128;
    __shared__ __align__(16) float Ws[32 * 132];
    __shared__ __align__(16) float Xs[32 * 132];
    int tx = threadIdx.x & 15, ty = threadIdx.x >> 4;
    float acc[8][8];
    {
        float bias[8];
        #pragma unroll
        for (int i = 0; i < 8; i++) bias[i] = d_bias[o0 + ty * 8 + i];
        #pragma unroll
        for (int j = 0; j < 8; j++)
            #pragma unroll
            for (int i = 0; i < 8; i++) acc[j][i] = bias[i];
    }
    for (int c0 = 0; c0 < 128; c0 += 32) {
        __syncthreads();
        for (int t = threadIdx.x; t < 32 * 128; t += 256) {
            int cc = t >> 7, oo = t & 127;
            Ws[cc * 132 + oo] = d_WT[(c0 + cc) * 384 + o0 + oo];
            Xs[cc * 132 + oo] = x[(b * 128 + c0 + cc) * NN + n0 + oo];
        }
        __syncthreads();
        #pragma unroll
        for (int cc = 0; cc < 32; cc++) {
            float4 w0 = *(const float4*)(Ws + cc * 132 + ty * 8);
            float4 w1 = *(const float4*)(Ws + cc * 132 + ty * 8 + 4);
            #pragma unroll
            for (int j = 0; j < 8; j++) {
                float xv = Xs[cc * 132 + tx + 16 * j];
                acc[j][0] = fmaf(w0.x, xv, acc[j][0]);
                acc[j][1] = fmaf(w0.y, xv, acc[j][1]);
                acc[j][2] = fmaf(w0.z, xv, acc[j][2]);
                acc[j][3] = fmaf(w0.w, xv, acc[j][3]);
                acc[j][4] = fmaf(w1.x, xv, acc[j][4]);
                acc[j][5] = fmaf(w1.y, xv, acc[j][5]);
                acc[j][6] = fmaf(w1.z, xv, acc[j][6]);
                acc[j][7] = fmaf(w1.w, xv, acc[j][7]);
            }
        }
    }
    #pragma unroll
    for (int j = 0; j < 8; j++) {
        int n = n0 + tx + 16 * j;
        float* dp = d_PQA + (b * NN + n) * 384 + o0 + ty * 8;
        *(float4*)dp       = make_float4(acc[j][0], acc[j][1], acc[j][2], acc[j][3]);
        *(float4*)(dp + 4) = make_float4(acc[j][4], acc[j][5], acc[j][6], acc[j][7]);
    }
}

// ---------------- k4: per-point attention ----------------
__global__ void __launch_bounds__(128) attn_kernel(const float* __restrict__ x) {
    int n = blockIdx.x, b = blockIdx.y;
    int c = threadIdx.x, g = c >> 5;
    __shared__ float fS[9 * 132];
    __shared__ float sS[4 * 81];
    __shared__ float awS[36], tS[36];
    __shared__ int idxS[9];
    int base = (b * NN + n) * 384;
    if (c < 9)  idxS[c] = d_knn_buf[(b * NN + n) * NK + c];
    if (c < 36) awS[c] = d_PQA[base + 256 + c];
    __syncthreads();
    float P = d_PQA[base + c];
    float e9[9];
    #pragma unroll
    for (int k = 0; k < 9; k++) {
        float f = P - d_PQA[(b * NN + idxS[k]) * 384 + 128 + c];
        fS[k * 132 + c] = f;
        e9[k] = f > 0.f ? f : expm1f(f);
    }
    if (c < 4) {
        float* row = awS + c * 9;
        float mx = row[0];
        #pragma unroll
        for (int k = 1; k < 9; k++) mx = fmaxf(mx, row[k]);
        float sm = 0.f;
        #pragma unroll
        for (int k = 0; k < 9; k++) { float e = expf(row[k] - mx); row[k] = e; sm += e; }
        float inv = 1.f / sm;
        #pragma unroll
        for (int k = 0; k < 9; k++) row[k] *= inv;
    }
    __syncthreads();
    for (int t = c; t < 324; t += 128) {
        int g2 = t / 81, p = t % 81, k = p / 9, j = p % 9;
        const float* fa = fS + k * 132 + g2 * 32;
        const float* fb = fS + j * 132 + g2 * 32;
        float s = 0.f;
        #pragma unroll
        for (int q = 0; q < 32; q++) s = fmaf(fa[q], fb[q], s);
        sS[g2 * 81 + p] = s * 0.17677669529663689f;
    }
    __syncthreads();
    if (c < 36) {
        float* row = sS + (c / 9) * 81 + (c % 9) * 9;
        float mx = row[0];
        #pragma unroll
        for (int j = 1; j < 9; j++) mx = fmaxf(mx, row[j]);
        float sm = 0.f;
        #pragma unroll
        for (int j = 0; j < 9; j++) { float e = expf(row[j] - mx); row[j] = e; sm += e; }
        float inv = 1.f / sm;
        #pragma unroll
        for (int j = 0; j < 9; j++) row[j] *= inv;
    }
    __syncthreads();
    if (c < 36) {
        int g2 = c / 9, j = c % 9;
        float tv = 0.f;
        #pragma unroll
        for (int k = 0; k < 9; k++) tv = fmaf(awS[g2 * 9 + k], sS[g2 * 81 + k * 9 + j], tv);
        tS[c] = tv;
    }
    __syncthreads();
    float lf = 0.f;
    #pragma unroll
    for (int j = 0; j < 9; j++) lf = fmaf(tS[g * 9 + j], e9[j], lf);
    float yv = lf + x[(b * 128 + c) * NN + n];
    d_Y[(b * NN + n) * 128 + c] = yv;
    float s1 = yv, s2 = yv * yv;
    #pragma unroll
    for (int off = 16; off; off >>= 1) {
        s1 += __shfl_xor_sync(0xffffffffu, s1, off);
        s2 += __shfl_xor_sync(0xffffffffu, s2, off);
    }
    if ((c & 31) == 0) {
        d_gnp_s[(b * 4 + g) * NN + n] = s1;
        d_gnp_q[(b * 4 + g) * NN + n] = s2;
    }
}

// ---------------- k5: GN stats ----------------
__global__ void gn_stats_kernel() {
    int bg = blockIdx.x;
    __shared__ double sh[256], sh2[256];
    double s = 0.0, q = 0.0;
    for (int i = threadIdx.x; i < NN; i += 256) {
        s += (double)d_gnp_s[bg * NN + i];
        q += (double)d_gnp_q[bg * NN + i];
    }
    sh[threadIdx.x] = s; sh2[threadIdx.x] = q;
    __syncthreads();
    for (int off = 128; off; off >>= 1) {
        if (threadIdx.x < off) { sh[threadIdx.x] += sh[threadIdx.x + off]; sh2[threadIdx.x] += sh2[threadIdx.x + off]; }
        __syncthreads();
    }
    if (threadIdx.x == 0) {
        double cnt = 32.0 * NN;
        double mean = sh[0] / cnt;
        double var = sh2[0] / cnt - mean * mean;
        d_gnm[bg] = (float)mean;
        d_gni[bg] = (float)(1.0 / sqrt(var + 1e-5));
    }
}

// ---------------- k6: fold GN into conv weights ----------------
__global__ void prepw_kernel(const float* __restrict__ conv_w, const float* __restrict__ conv_b,
                             const float* __restrict__ gn_g, const float* __restrict__ gn_b) {
    int b = blockIdx.x, o = threadIdx.x;
    float e = conv_b[o];
    for (int c = 0; c < 128; c++) {
        int g = c >> 5;
        float inv = d_gni[b * 4 + g];
        float A = gn_g[c] * inv;
        float D = gn_b[c] - d_gnm[b * 4 + g] * A;
        float w = conv_w[o * 128 + c];
        e = fmaf(w, D, e);
        d_WPT[(b * 128 + c) * 128 + o] = w * A;
    }
    d_E[b * 128 + o] = e;
}

// ---------------- k7: GEMM B ----------------
__global__ void __launch_bounds__(256) gemmB_kernel() {
    int b = blockIdx.y, n0 = blockIdx.x * 128;
    __shared__ __align__(16) float Ws[32 * 132];
    __shared__ __align__(16) float Ys[128 * 33];
    int tx = threadIdx.x & 15, ty = threadIdx.x >> 4;
    float acc[8][8];
    {
        float eb[8];
        #pragma unroll
        for (int i = 0; i < 8; i++) eb[i] = d_E[b * 128 + ty * 8 + i];
        #pragma unroll
        for (int j = 0; j < 8; j++)
            #pragma unroll
            for (int i = 0; i < 8; i++) acc[j][i] = eb[i];
    }
    for (int c0 = 0; c0 < 128; c0 += 32) {
        __syncthreads();
        for (int t = threadIdx.x; t < 32 * 128; t += 256) {
            int cc = t >> 7, oo = t & 127;
            Ws[cc * 132 + oo] = d_WPT[(b * 128 + c0 + cc) * 128 + oo];
            int nl = t >> 5, cl = t & 31;
            Ys[nl * 33 + cl] = d_Y[(b * NN + n0 + nl) * 128 + c0 + cl];
        }
        __syncthreads();
        #pragma unroll
        for (int cc = 0; cc < 32; cc++) {
            float4 w0 = *(const float4*)(Ws + cc * 132 + ty * 8);
            float4 w1 = *(const float4*)(Ws + cc * 132 + ty * 8 + 4);
            #pragma unroll
            for (int j = 0; j < 8; j++) {
                float yv = Ys[(tx + 16 * j) * 33 + cc];
                acc[j][0] = fmaf(w0.x, yv, acc[j][0]);
                acc[j][1] = fmaf(w0.y, yv, acc[j][1]);
                acc[j][2] = fmaf(w0.z, yv, acc[j][2]);
                acc[j][3] = fmaf(w0.w, yv, acc[j][3]);
                acc[j][4] = fmaf(w1.x, yv, acc[j][4]);
                acc[j][5] = fmaf(w1.y, yv, acc[j][5]);
                acc[j][6] = fmaf(w1.z, yv, acc[j][6]);
                acc[j][7] = fmaf(w1.w, yv, acc[j][7]);
            }
        }
    }
    #pragma unroll
    for (int j = 0; j < 8; j++) {
        int n = n0 + tx + 16 * j;
        #pragma unroll
        for (int i = 0; i < 8; i++)
            d_Z[(b * 128 + ty * 8 + i) * NN + n] = acc[j][i];
    }
    float* red = Ys;
    __syncthreads();
    #pragma unroll
    for (int i = 0; i < 8; i++) {
        float s = 0.f, q = 0.f;
        #pragma unroll
        for (int j = 0; j < 8; j++) { s += acc[j][i]; q = fmaf(acc[j][i], acc[j][i], q); }
        red[(ty * 8 + i) * 16 + tx] = s;
        red[2048 + (ty * 8 + i) * 16 + tx] = q;
    }
    __syncthreads();
    if (threadIdx.x < 128) {
        int o = threadIdx.x;
        float s = 0.f, q = 0.f;
        #pragma unroll
        for (int t = 0; t < 16; t++) { s += red[o * 16 + t]; q += red[2048 + o * 16 + t]; }
        int blk = blockIdx.y * 32 + blockIdx.x;
        d_bnp_s[o * 128 + blk] = s;
        d_bnp_q[o * 128 + blk] = q;
    }
}

// ---------------- k8: BN stats ----------------
__global__ void bn_stats_kernel() {
    int o = threadIdx.x;
    double s = 0.0, q = 0.0;
    for (int k = 0; k < 128; k++) { s += (double)d_bnp_s[o * 128 + k]; q += (double)d_bnp_q[o * 128 + k]; }
    double cnt = (double)(NB * NN);
    double mean = s / cnt;
    double var = q / cnt - mean * mean;
    d_bnm[o] = (float)mean;
    d_bni[o] = (float)(1.0 / sqrt(var + 1e-5));
}

// ---------------- k9: BN apply + relu ----------------
__global__ void final_kernel(const float* __restrict__ bn_g, const float* __restrict__ bn_b,
                             float* __restrict__ out) {
    int i = blockIdx.x * 256 + threadIdx.x;
    int o = (i >> 12) & 127;
    float v = (d_Z[i] - d_bnm[o]) * d_bni[o] * bn_g[o] + bn_b[o];
    out[i] = fmaxf(v, 0.f);
}

extern "C" void kernel_launch(void* const* d_in, const int* in_sizes, int n_in,
                              void* d_out, int out_size) {
    const float* x      = (const float*)d_in[0];
    const float* w_lin  = (const float*)d_in[1];
    const float* b_lin  = (const float*)d_in[2];
    const float* w_aw   = (const float*)d_in[3];
    const float* b_aw   = (const float*)d_in[4];
    const float* gn_g   = (const float*)d_in[5];
    const float* gn_b   = (const float*)d_in[6];
    const float* conv_w = (const float*)d_in[7];
    const float* conv_b = (const float*)d_in[8];
    const float* bn_g   = (const float*)d_in[9];
    const float* bn_b   = (const float*)d_in[10];
    float* out = (float*)d_out;

    cudaFuncSetAttribute(knn_kernel, cudaFuncAttributeMaxDynamicSharedMemorySize, KNN_SMEM_BYTES);

    prep_kernel<<<192, 256>>>(w_lin, b_lin, w_aw, b_aw);
    xx_kernel<<<64, 256>>>(x);
    cvt_kernel<<<dim3(128, 4, 4), 256>>>(x);
    knn_kernel<<<dim3(32, 4), 512, KNN_SMEM_BYTES>>>();
    gemmA_kernel<<<dim3(32, 4, 3), 256>>>(x);
    attn_kernel<<<dim3(4096, 4), 128>>>(x);
    gn_stats_kernel<<<16, 256>>>();
    prepw_kernel<<<4, 128>>>(conv_w, conv_b, gn_g, gn_b);
    gemmB_kernel<<<dim3(32, 4), 256>>>();
    bn_stats_kernel<<<1, 128>>>();
    final_kernel<<<8192, 256>>>(bn_g, bn_b, out);
}

// round 15
// speedup vs baseline: 2.7747x; 1.0060x over previous
#include <cuda_runtime.h>
#include <cuda_bf16.h>
#include <stdint.h>
#include <math.h>

#define NB 4
#define NC 128
#define NN 4096
#define NK 9

// ---------------- device scratch ----------------
__device__ __align__(16) float d_WT[128 * 384];
__device__ float d_bias[384];
__device__ __align__(16) float d_xx[NB * NN];
__device__ int   d_knn_buf[NB * NN * NK];
__device__ __align__(16) float d_PQA[NB * NN * 384];
__device__ __align__(16) float d_Y[NB * NN * 128];
__device__ __align__(16) float d_Z[NB * 128 * NN];
__device__ float d_gnp_s[16 * NN];
__device__ float d_gnp_q[16 * NN];
__device__ float d_gnm[16], d_gni[16];
__device__ __align__(16) float d_WPT[NB * 128 * 128];
__device__ float d_E[NB * 128];
__device__ float d_bnp_s[128 * 128], d_bnp_q[128 * 128];
__device__ float d_bnm[128], d_bni[128];
// bf16 split of x, transposed to [b][n][c]
__device__ __align__(16) __nv_bfloat16 d_XH[NB * NN * 128];
__device__ __align__(16) __nv_bfloat16 d_XL[NB * NN * 128];

// ---------------- helpers ----------------
__device__ __forceinline__ uint32_t smem_u32(const void* p) {
    uint32_t a;
    asm("{ .reg .u64 t; cvta.to.shared.u64 t, %1; cvt.u32.u64 %0, t; }" : "=r"(a) : "l"(p));
    return a;
}
__device__ __forceinline__ void cpasync16(void* dst, const void* src) {
    unsigned s = (unsigned)__cvta_generic_to_shared(dst);
    asm volatile("cp.async.cg.shared.global [%0], [%1], 16;" :: "r"(s), "l"(src) : "memory");
}
#define CP_COMMIT() asm volatile("cp.async.commit_group;" ::: "memory")
#define CP_WAIT0()  asm volatile("cp.async.wait_group 0;" ::: "memory")

__device__ __forceinline__ void ldm_x4(uint32_t* r, uint32_t addr) {
    asm volatile("ldmatrix.sync.aligned.m8n8.x4.shared.b16 {%0,%1,%2,%3}, [%4];"
                 : "=r"(r[0]), "=r"(r[1]), "=r"(r[2]), "=r"(r[3]) : "r"(addr));
}
__device__ __forceinline__ void mma_bf16(float* d, const uint32_t* a, uint32_t b0, uint32_t b1) {
    asm volatile("mma.sync.aligned.m16n8k16.row.col.f32.bf16.bf16.f32 "
                 "{%0,%1,%2,%3}, {%4,%5,%6,%7}, {%8,%9}, {%0,%1,%2,%3};"
                 : "+f"(d[0]), "+f"(d[1]), "+f"(d[2]), "+f"(d[3])
                 : "r"(a[0]), "r"(a[1]), "r"(a[2]), "r"(a[3]), "r"(b0), "r"(b1));
}

// key: descending by value, ties -> smaller index first (matches lax.top_k)
__device__ __forceinline__ unsigned long long enckey(float v, int m) {
    unsigned u = __float_as_uint(v);
    unsigned mask = ((int)u < 0) ? 0xFFFFFFFFu : 0x80000000u;
    u ^= mask;
    return ((unsigned long long)u << 32) | (unsigned)(~m);
}
// decode the value half of a key back to float (for the fast-path threshold)
__device__ __forceinline__ float dec_th(unsigned long long key) {
    uint32_t hi = (uint32_t)(key >> 32);
    return (hi & 0x80000000u) ? __uint_as_float(hi ^ 0x80000000u) : __uint_as_float(~hi);
}
// enckey(-inf, 0x7fffffff): value 0x007FFFFF, index ~0x7fffffff
#define NEG_KEY 0x007FFFFF80000000ull

// ---------------- k0: combined weights (transposed) ----------------
__global__ void prep_kernel(const float* __restrict__ w_lin, const float* __restrict__ b_lin,
                            const float* __restrict__ w_aw, const float* __restrict__ b_aw) {
    int i = blockIdx.x * 256 + threadIdx.x;
    if (i >= 384 * 128) return;
    int o = i % 384, c = i / 384;
    float w = 0.f;
    if (o < 128)      w = w_lin[o * 256 + c] + w_lin[o * 256 + 128 + c];
    else if (o < 256) w = w_lin[(o - 128) * 256 + 128 + c];
    else if (o < 292) w = w_aw[(o - 256) * 128 + c];
    d_WT[c * 384 + o] = w;
    if (c == 0) {
        float bv = 0.f;
        if (o < 128) bv = b_lin[o];
        else if (o >= 256 && o < 292) bv = b_aw[o - 256];
        d_bias[o] = bv;
    }
}

// ---------------- k1: xx ----------------
__global__ void xx_kernel(const float* __restrict__ x) {
    int i = blockIdx.x * 256 + threadIdx.x;
    int b = i >> 12, n = i & (NN - 1);
    float s = 0.f;
    #pragma unroll 8
    for (int c = 0; c < 128; c++) {
        float v = x[(b * 128 + c) * NN + n];
        s = fmaf(v, v, s);
    }
    d_xx[i] = s;
}

// ---------------- k1b: transpose + bf16 split ----------------
__global__ void cvt_kernel(const float* __restrict__ x) {
    __shared__ float t[32][33];
    int b = blockIdx.z, ct = blockIdx.y, nt = blockIdx.x;
    int tx = threadIdx.x & 31, ty = threadIdx.x >> 5;
    #pragma unroll
    for (int it = 0; it < 4; it++) {
        int c = ct * 32 + ty + it * 8, n = nt * 32 + tx;
        t[ty + it * 8][tx] = x[(b * 128 + c) * NN + n];
    }
    __syncthreads();
    #pragma unroll
    for (int it = 0; it < 4; it++) {
        int nl = ty + it * 8, c = tx;
        float v = t[c][nl];
        __nv_bfloat16 h = __float2bfloat16(v);
        __nv_bfloat16 l = __float2bfloat16(v - __bfloat162float(h));
        int gi = (b * NN + nt * 32 + nl) * 128 + ct * 32 + c;
        d_XH[gi] = h;
        d_XL[gi] = l;
    }
}

// ---------------- k2: KNN via mma.sync bf16 (3-term split) ----------------
// Block = 128 query rows, 512 threads (16 warps: warpM=wid&7 -> 16 rows,
// warpN=wid>>3 -> 64 cols in two 32-col halves).
// R14: merged ks loop from R13 kept (Bhi feeds Ahi+Alo, Blo reuses frag regs)
// but with the CORRECT per-lane swizzle decomposition: for chunk c = 2ks+x,
//   (c ^ sw)<<4 = ((x^sw0)<<4)  [loop-invariant]  +  ((ks ^ (sw>>1))<<5)
// with ks uniform across lanes (R13 wrongly iterated the physical chunk,
// mixing logical k-steps across lanes inside one ldmatrix -> rel_err 0.18).
#define SM_XX  0
#define SM_AHI 1024
#define SM_ALO (SM_AHI + 32768)
#define SM_B   (SM_ALO + 32768)
#define SM_BUF 65536
#define KNN_SMEM_BYTES (SM_B + 2 * SM_BUF)   // 197632

__device__ __forceinline__ void fill_rows(char* smem, int dstoff, const __nv_bfloat16* src, int tid) {
    #pragma unroll
    for (int i = 0; i < 4; i++) {
        int idx = i * 512 + tid;            // 2048 chunks = 128 rows x 256B
        int r = idx >> 4, c = idx & 15;
        cpasync16(smem + dstoff + r * 256 + ((c ^ (r & 7)) << 4), src + r * 128 + c * 8);
    }
}

#define INSERT9(Lst, thf, keyv) do { \
    unsigned long long _k = (keyv); \
    _Pragma("unroll") \
    for (int _q = 0; _q < 9; _q++) { \
        unsigned long long _c = (Lst)[_q]; \
        if (_k > _c) { (Lst)[_q] = _k; _k = _c; } \
    } \
    (thf) = dec_th((Lst)[8]); \
} while (0)

__global__ void __launch_bounds__(512) knn_kernel() {
    extern __shared__ char smc[];
    const uint32_t sb = smem_u32(smc);
    const int b = blockIdx.y, n0 = blockIdx.x * 128;
    const int tid = threadIdx.x, wid = tid >> 5, lane = tid & 31;
    const int warpM = wid & 7, warpN = wid >> 3;

    // prolog: A (queries, hi+lo), B tile 0 (hi+lo), xx tile 0
    fill_rows(smc, SM_AHI, d_XH + (b * NN + n0) * 128, tid);
    fill_rows(smc, SM_ALO, d_XL + (b * NN + n0) * 128, tid);
    fill_rows(smc, SM_B,           d_XH + (b * NN) * 128, tid);
    fill_rows(smc, SM_B + 32768,   d_XL + (b * NN) * 128, tid);
    if (tid < 32) cpasync16(smc + SM_XX + tid * 16, d_xx + b * NN + tid * 4);
    CP_COMMIT();

    // ldmatrix address components (per-lane decomposed swizzle)
    const int arow = warpM * 16 + (lane & 15);
    const int asw = arow & 7;
    const int ahalf = lane >> 4;
    const uint32_t aswh = (uint32_t)(asw >> 1);                   // per-lane high swizzle bits
    const uint32_t aInv = (uint32_t)((ahalf ^ (asw & 1)) << 4);   // loop-invariant bit-0 term
    const uint32_t aHb = sb + SM_AHI + (uint32_t)(arow * 256) + aInv;
    const uint32_t aLb = sb + SM_ALO + (uint32_t)(arow * 256) + aInv;
    const int bmtx = lane >> 3;
    const int brow_loc = (lane & 7) + (bmtx & 1) * 8;
    const int bchunk_add = bmtx >> 1;
    const int bsw = brow_loc & 7;
    const uint32_t bswh = (uint32_t)(bsw >> 1);
    const uint32_t bInv = (uint32_t)((bchunk_add ^ (bsw & 1)) << 4);

    unsigned long long L0[9], L1[9];
    #pragma unroll
    for (int q = 0; q < 9; q++) { L0[q] = NEG_KEY; L1[q] = NEG_KEY; }
    float thf0 = -INFINITY, thf1 = -INFINITY;

    for (int mt = 0; mt < 32; mt++) {
        const int m0 = mt * 128, s = mt & 1;
        CP_WAIT0();
        __syncthreads();

        if (mt < 31) {
            int sn = (mt + 1) & 1, m0n = m0 + 128;
            fill_rows(smc, SM_B + sn * SM_BUF,         d_XH + (b * NN + m0n) * 128, tid);
            fill_rows(smc, SM_B + sn * SM_BUF + 32768, d_XL + (b * NN + m0n) * 128, tid);
            if (tid < 32) cpasync16(smc + SM_XX + sn * 512 + tid * 16, d_xx + b * NN + m0n + tid * 4);
            CP_COMMIT();
        }

        const uint32_t bh = sb + SM_B + s * SM_BUF;
        const uint32_t bl = bh + 32768;
        const float* xxS = (const float*)(smc + SM_XX + s * 512);

        #pragma unroll
        for (int half = 0; half < 2; half++) {
            float acc[4][4];
            #pragma unroll
            for (int g = 0; g < 4; g++)
                #pragma unroll
                for (int i = 0; i < 4; i++) acc[g][i] = 0.f;

            const int rbase = warpN * 64 + half * 32 + brow_loc;
            const uint32_t b0h = bh + (uint32_t)(rbase * 256) + bInv;
            const uint32_t b1h = bh + (uint32_t)((rbase + 16) * 256) + bInv;
            const uint32_t b0l = bl + (uint32_t)(rbase * 256) + bInv;
            const uint32_t b1l = bl + (uint32_t)((rbase + 16) * 256) + bInv;

            // merged loop over LOGICAL k-steps (uniform across lanes)
            #pragma unroll
            for (int ks = 0; ks < 8; ks++) {
                const uint32_t aoff = (uint32_t)((ks ^ aswh) << 5);  // LOP3-imm + shift
                const uint32_t boff = (uint32_t)((ks ^ bswh) << 5);
                uint32_t afh[4], afl[4], bfa[4], bfb[4];
                ldm_x4(afh, aHb + aoff);
                ldm_x4(afl, aLb + aoff);
                ldm_x4(bfa, b0h + boff);
                ldm_x4(bfb, b1h + boff);
                mma_bf16(acc[0], afh, bfa[0], bfa[2]);
                mma_bf16(acc[1], afh, bfa[1], bfa[3]);
                mma_bf16(acc[2], afh, bfb[0], bfb[2]);
                mma_bf16(acc[3], afh, bfb[1], bfb[3]);
                mma_bf16(acc[0], afl, bfa[0], bfa[2]);
                mma_bf16(acc[1], afl, bfa[1], bfa[3]);
                mma_bf16(acc[2], afl, bfb[0], bfb[2]);
                mma_bf16(acc[3], afl, bfb[1], bfb[3]);
                ldm_x4(bfa, b0l + boff);
                ldm_x4(bfb, b1l + boff);
                mma_bf16(acc[0], afh, bfa[0], bfa[2]);
                mma_bf16(acc[1], afh, bfa[1], bfa[3]);
                mma_bf16(acc[2], afh, bfb[0], bfb[2]);
                mma_bf16(acc[3], afh, bfb[1], bfb[3]);
            }

            // selection: col groups g -> cols warpN*64 + half*32 + g*8 + (lane&3)*2 + {0,1}
            const int colb = warpN * 64 + half * 32 + (lane & 3) * 2;
            #pragma unroll
            for (int g = 0; g < 4; g++) {
                int nl = colb + g * 8;
                float xa = xxS[nl], xb2 = xxS[nl + 1];
                int ma = m0 + nl;
                float v;
                v = fmaf(2.f, acc[g][0], -xa);
                if (v >= thf0) INSERT9(L0, thf0, enckey(v, ma));
                v = fmaf(2.f, acc[g][1], -xb2);
                if (v >= thf0) INSERT9(L0, thf0, enckey(v, ma + 1));
                v = fmaf(2.f, acc[g][2], -xa);
                if (v >= thf1) INSERT9(L1, thf1, enckey(v, ma));
                v = fmaf(2.f, acc[g][3], -xb2);
                if (v >= thf1) INSERT9(L1, thf1, enckey(v, ma + 1));
            }
        }
    }

    // merge: 8 lists per row (2 warpN x 4 lane&3), reuse B area as scratch
    __syncthreads();
    unsigned long long* M = (unsigned long long*)(smc + SM_B);
    {
        int r0 = warpM * 16 + (lane >> 2), src = warpN * 4 + (lane & 3);
        #pragma unroll
        for (int q = 0; q < 9; q++) {
            M[(r0 * 8 + src) * 9 + q]       = L0[q];
            M[((r0 + 8) * 8 + src) * 9 + q] = L1[q];
        }
    }
    __syncthreads();
    if (tid < 128) {
        const unsigned long long* base = M + tid * 72;
        int h[8];
        #pragma unroll
        for (int l = 0; l < 8; l++) h[l] = 0;
        for (int q = 0; q < 9; q++) {
            unsigned long long best = 0; int bl2 = 0;
            #pragma unroll
            for (int l = 0; l < 8; l++) {
                if (h[l] < 9) {
                    unsigned long long kk = base[l * 9 + h[l]];
                    if (kk > best) { best = kk; bl2 = l; }
                }
            }
            h[bl2]++;
            d_knn_buf[(b * NN + n0 + tid) * NK + q] = (int)(~(unsigned)(best & 0xFFFFFFFFu));
        }
    }
}

// ---------------- k3: GEMM A ----------------
__global__ void __launch_bounds__(256) gemmA_kernel(const float* __restrict__ x) {
    int b = blockIdx.y, n0 = blockIdx.x * 128, o0 = blockIdx.z * 128;
    __shared__ __align__(16) float Ws[32 * 132];
    __shared__ __align__(16) float Xs[32 * 132];
    int tx = threadIdx.x & 15, ty = threadIdx.x >> 4;
    float acc[8][8];
    {
        float bias[8];
        #pragma unroll
        for (int i = 0; i < 8; i++) bias[i] = d_bias[o0 + ty * 8 + i];
        #pragma unroll
        for (int j = 0; j < 8; j++)
            #pragma unroll
            for (int i = 0; i < 8; i++) acc[j][i] = bias[i];
    }
    for (int c0 = 0; c0 < 128; c0 += 32) {
        __syncthreads();
        for (int t = threadIdx.x; t < 32 * 128; t += 256) {
            int cc = t >> 7, oo = t & 127;
            Ws[cc * 132 + oo] = d_WT[(c0 + cc) * 384 + o0 + oo];
            Xs[cc * 132 + oo] = x[(b * 128 + c0 + cc) * NN + n0 + oo];
        }
        __syncthreads();
        #pragma unroll
        for (int cc = 0; cc < 32; cc++) {
            float4 w0 = *(const float4*)(Ws + cc * 132 + ty * 8);
            float4 w1 = *(const float4*)(Ws + cc * 132 + ty * 8 + 4);
            #pragma unroll
            for (int j = 0; j < 8; j++) {
                float xv = Xs[cc * 132 + tx + 16 * j];
                acc[j][0] = fmaf(w0.x, xv, acc[j][0]);
                acc[j][1] = fmaf(w0.y, xv, acc[j][1]);
                acc[j][2] = fmaf(w0.z, xv, acc[j][2]);
                acc[j][3] = fmaf(w0.w, xv, acc[j][3]);
                acc[j][4] = fmaf(w1.x, xv, acc[j][4]);
                acc[j][5] = fmaf(w1.y, xv, acc[j][5]);
                acc[j][6] = fmaf(w1.z, xv, acc[j][6]);
                acc[j][7] = fmaf(w1.w, xv, acc[j][7]);
            }
        }
    }
    #pragma unroll
    for (int j = 0; j < 8; j++) {
        int n = n0 + tx + 16 * j;
        float* dp = d_PQA + (b * NN + n) * 384 + o0 + ty * 8;
        *(float4*)dp       = make_float4(acc[j][0], acc[j][1], acc[j][2], acc[j][3]);
        *(float4*)(dp + 4) = make_float4(acc[j][4], acc[j][5], acc[j][6], acc[j][7]);
    }
}

// ---------------- k4: per-point attention ----------------
__global__ void __launch_bounds__(128) attn_kernel(const float* __restrict__ x) {
    int n = blockIdx.x, b = blockIdx.y;
    int c = threadIdx.x, g = c >> 5;
    __shared__ float fS[9 * 132];
    __shared__ float sS[4 * 81];
    __shared__ float awS[36], tS[36];
    __shared__ int idxS[9];
    int base = (b * NN + n) * 384;
    if (c < 9)  idxS[c] = d_knn_buf[(b * NN + n) * NK + c];
    if (c < 36) awS[c] = d_PQA[base + 256 + c];
    __syncthreads();
    float P = d_PQA[base + c];
    float e9[9];
    #pragma unroll
    for (int k = 0; k < 9; k++) {
        float f = P - d_PQA[(b * NN + idxS[k]) * 384 + 128 + c];
        fS[k * 132 + c] = f;
        e9[k] = f > 0.f ? f : expm1f(f);
    }
    if (c < 4) {
        float* row = awS + c * 9;
        float mx = row[0];
        #pragma unroll
        for (int k = 1; k < 9; k++) mx = fmaxf(mx, row[k]);
        float sm = 0.f;
        #pragma unroll
        for (int k = 0; k < 9; k++) { float e = expf(row[k] - mx); row[k] = e; sm += e; }
        float inv = 1.f / sm;
        #pragma unroll
        for (int k = 0; k < 9; k++) row[k] *= inv;
    }
    __syncthreads();
    for (int t = c; t < 324; t += 128) {
        int g2 = t / 81, p = t % 81, k = p / 9, j = p % 9;
        const float* fa = fS + k * 132 + g2 * 32;
        const float* fb = fS + j * 132 + g2 * 32;
        float s = 0.f;
        #pragma unroll
        for (int q = 0; q < 32; q++) s = fmaf(fa[q], fb[q], s);
        sS[g2 * 81 + p] = s * 0.17677669529663689f;
    }
    __syncthreads();
    if (c < 36) {
        float* row = sS + (c / 9) * 81 + (c % 9) * 9;
        float mx = row[0];
        #pragma unroll
        for (int j = 1; j < 9; j++) mx = fmaxf(mx, row[j]);
        float sm = 0.f;
        #pragma unroll
        for (int j = 0; j < 9; j++) { float e = expf(row[j] - mx); row[j] = e; sm += e; }
        float inv = 1.f / sm;
        #pragma unroll
        for (int j = 0; j < 9; j++) row[j] *= inv;
    }
    __syncthreads();
    if (c < 36) {
        int g2 = c / 9, j = c % 9;
        float tv = 0.f;
        #pragma unroll
        for (int k = 0; k < 9; k++) tv = fmaf(awS[g2 * 9 + k], sS[g2 * 81 + k * 9 + j], tv);
        tS[c] = tv;
    }
    __syncthreads();
    float lf = 0.f;
    #pragma unroll
    for (int j = 0; j < 9; j++) lf = fmaf(tS[g * 9 + j], e9[j], lf);
    float yv = lf + x[(b * 128 + c) * NN + n];
    d_Y[(b * NN + n) * 128 + c] = yv;
    float s1 = yv, s2 = yv * yv;
    #pragma unroll
    for (int off = 16; off; off >>= 1) {
        s1 += __shfl_xor_sync(0xffffffffu, s1, off);
        s2 += __shfl_xor_sync(0xffffffffu, s2, off);
    }
    if ((c & 31) == 0) {
        d_gnp_s[(b * 4 + g) * NN + n] = s1;
        d_gnp_q[(b * 4 + g) * NN + n] = s2;
    }
}

// ---------------- k5: GN stats ----------------
__global__ void gn_stats_kernel() {
    int bg = blockIdx.x;
    __shared__ double sh[256], sh2[256];
    double s = 0.0, q = 0.0;
    for (int i = threadIdx.x; i < NN; i += 256) {
        s += (double)d_gnp_s[bg * NN + i];
        q += (double)d_gnp_q[bg * NN + i];
    }
    sh[threadIdx.x] = s; sh2[threadIdx.x] = q;
    __syncthreads();
    for (int off = 128; off; off >>= 1) {
        if (threadIdx.x < off) { sh[threadIdx.x] += sh[threadIdx.x + off]; sh2[threadIdx.x] += sh2[threadIdx.x + off]; }
        __syncthreads();
    }
    if (threadIdx.x == 0) {
        double cnt = 32.0 * NN;
        double mean = sh[0] / cnt;
        double var = sh2[0] / cnt - mean * mean;
        d_gnm[bg] = (float)mean;
        d_gni[bg] = (float)(1.0 / sqrt(var + 1e-5));
    }
}

// ---------------- k6: fold GN into conv weights ----------------
__global__ void prepw_kernel(const float* __restrict__ conv_w, const float* __restrict__ conv_b,
                             const float* __restrict__ gn_g, const float* __restrict__ gn_b) {
    int b = blockIdx.x, o = threadIdx.x;
    float e = conv_b[o];
    for (int c = 0; c < 128; c++) {
        int g = c >> 5;
        float inv = d_gni[b * 4 + g];
        float A = gn_g[c] * inv;
        float D = gn_b[c] - d_gnm[b * 4 + g] * A;
        float w = conv_w[o * 128 + c];
        e = fmaf(w, D, e);
        d_WPT[(b * 128 + c) * 128 + o] = w * A;
    }
    d_E[b * 128 + o] = e;
}

// ---------------- k7: GEMM B ----------------
__global__ void __launch_bounds__(256) gemmB_kernel() {
    int b = blockIdx.y, n0 = blockIdx.x * 128;
    __shared__ __align__(16) float Ws[32 * 132];
    __shared__ __align__(16) float Ys[128 * 33];
    int tx = threadIdx.x & 15, ty = threadIdx.x >> 4;
    float acc[8][8];
    {
        float eb[8];
        #pragma unroll
        for (int i = 0; i < 8; i++) eb[i] = d_E[b * 128 + ty * 8 + i];
        #pragma unroll
        for (int j = 0; j < 8; j++)
            #pragma unroll
            for (int i = 0; i < 8; i++) acc[j][i] = eb[i];
    }
    for (int c0 = 0; c0 < 128; c0 += 32) {
        __syncthreads();
        for (int t = threadIdx.x; t < 32 * 128; t += 256) {
            int cc = t >> 7, oo = t & 127;
            Ws[cc * 132 + oo] = d_WPT[(b * 128 + c0 + cc) * 128 + oo];
            int nl = t >> 5, cl = t & 31;
            Ys[nl * 33 + cl] = d_Y[(b * NN + n0 + nl) * 128 + c0 + cl];
        }
        __syncthreads();
        #pragma unroll
        for (int cc = 0; cc < 32; cc++) {
            float4 w0 = *(const float4*)(Ws + cc * 132 + ty * 8);
            float4 w1 = *(const float4*)(Ws + cc * 132 + ty * 8 + 4);
            #pragma unroll
            for (int j = 0; j < 8; j++) {
                float yv = Ys[(tx + 16 * j) * 33 + cc];
                acc[j][0] = fmaf(w0.x, yv, acc[j][0]);
                acc[j][1] = fmaf(w0.y, yv, acc[j][1]);
                acc[j][2] = fmaf(w0.z, yv, acc[j][2]);
                acc[j][3] = fmaf(w0.w, yv, acc[j][3]);
                acc[j][4] = fmaf(w1.x, yv, acc[j][4]);
                acc[j][5] = fmaf(w1.y, yv, acc[j][5]);
                acc[j][6] = fmaf(w1.z, yv, acc[j][6]);
                acc[j][7] = fmaf(w1.w, yv, acc[j][7]);
            }
        }
    }
    #pragma unroll
    for (int j = 0; j < 8; j++) {
        int n = n0 + tx + 16 * j;
        #pragma unroll
        for (int i = 0; i < 8; i++)
            d_Z[(b * 128 + ty * 8 + i) * NN + n] = acc[j][i];
    }
    float* red = Ys;
    __syncthreads();
    #pragma unroll
    for (int i = 0; i < 8; i++) {
        float s = 0.f, q = 0.f;
        #pragma unroll
        for (int j = 0; j < 8; j++) { s += acc[j][i]; q = fmaf(acc[j][i], acc[j][i], q); }
        red[(ty * 8 + i) * 16 + tx] = s;
        red[2048 + (ty * 8 + i) * 16 + tx] = q;
    }
    __syncthreads();
    if (threadIdx.x < 128) {
        int o = threadIdx.x;
        float s = 0.f, q = 0.f;
        #pragma unroll
        for (int t = 0; t < 16; t++) { s += red[o * 16 + t]; q += red[2048 + o * 16 + t]; }
        int blk = blockIdx.y * 32 + blockIdx.x;
        d_bnp_s[o * 128 + blk] = s;
        d_bnp_q[o * 128 + blk] = q;
    }
}

// ---------------- k8: BN stats ----------------
__global__ void bn_stats_kernel() {
    int o = threadIdx.x;
    double s = 0.0, q = 0.0;
    for (int k = 0; k < 128; k++) { s += (double)d_bnp_s[o * 128 + k]; q += (double)d_bnp_q[o * 128 + k]; }
    double cnt = (double)(NB * NN);
    double mean = s / cnt;
    double var = q / cnt - mean * mean;
    d_bnm[o] = (float)mean;
    d_bni[o] = (float)(1.0 / sqrt(var + 1e-5));
}

// ---------------- k9: BN apply + relu ----------------
__global__ void final_kernel(const float* __restrict__ bn_g, const float* __restrict__ bn_b,
                             float* __restrict__ out) {
    int i = blockIdx.x * 256 + threadIdx.x;
    int o = (i >> 12) & 127;
    float v = (d_Z[i] - d_bnm[o]) * d_bni[o] * bn_g[o] + bn_b[o];
    out[i] = fmaxf(v, 0.f);
}

extern "C" void kernel_launch(void* const* d_in, const int* in_sizes, int n_in,
                              void* d_out, int out_size) {
    const float* x      = (const float*)d_in[0];
    const float* w_lin  = (const float*)d_in[1];
    const float* b_lin  = (const float*)d_in[2];
    const float* w_aw   = (const float*)d_in[3];
    const float* b_aw   = (const float*)d_in[4];
    const float* gn_g   = (const float*)d_in[5];
    const float* gn_b   = (const float*)d_in[6];
    const float* conv_w = (const float*)d_in[7];
    const float* conv_b = (const float*)d_in[8];
    const float* bn_g   = (const float*)d_in[9];
    const float* bn_b   = (const float*)d_in[10];
    float* out = (float*)d_out;

    cudaFuncSetAttribute(knn_kernel, cudaFuncAttributeMaxDynamicSharedMemorySize, KNN_SMEM_BYTES);

    prep_kernel<<<192, 256>>>(w_lin, b_lin, w_aw, b_aw);
    xx_kernel<<<64, 256>>>(x);
    cvt_kernel<<<dim3(128, 4, 4), 256>>>(x);
    knn_kernel<<<dim3(32, 4), 512, KNN_SMEM_BYTES>>>();
    gemmA_kernel<<<dim3(32, 4, 3), 256>>>(x);
    attn_kernel<<<dim3(4096, 4), 128>>>(x);
    gn_stats_kernel<<<16, 256>>>();
    prepw_kernel<<<4, 128>>>(conv_w, conv_b, gn_g, gn_b);
    gemmB_kernel<<<dim3(32, 4), 256>>>();
    bn_stats_kernel<<<1, 128>>>();
    final_kernel<<<8192, 256>>>(bn_g, bn_b, out);
}